// round 13
// baseline (speedup 1.0000x reference)
#include <cuda_runtime.h>
#include <cuda_bf16.h>
#include <math.h>
#include <float.h>
#include <stdint.h>

// Problem constants
#define BATCH 2
#define SEQL  2048
#define EMB   1024
#define HEADS 16
#define DHEAD 64
#define FFN   4096
#define NTOK  (BATCH*SEQL)   // 4096
#define LN_EPS 1e-5f

// ================= scratch (device globals; no allocation allowed) ==========
__device__ __align__(16) __nv_bfloat16 g_xh [NTOK*EMB], g_xl [NTOK*EMB];
__device__ __align__(16) __nv_bfloat16 g_Wqvh[2*EMB*EMB], g_Wqvl[2*EMB*EMB]; // [N=2048][K=1024]
__device__ __align__(16) __nv_bfloat16 g_Woh[EMB*EMB],  g_Wol[EMB*EMB];
__device__ __align__(16) __nv_bfloat16 g_W1h[EMB*FFN],  g_W1l[EMB*FFN];   // [N=FFN][K=EMB]
__device__ __align__(16) __nv_bfloat16 g_W2h[EMB*FFN],  g_W2l[EMB*FFN];   // [N=EMB][K=FFN]
__device__ __align__(16) __nv_bfloat16 g_Qh [NTOK*EMB], g_Ql [NTOK*EMB];  // [b,h,l,d], pre-scaled 1/8
__device__ __align__(16) __nv_bfloat16 g_Vh [NTOK*EMB], g_Vl [NTOK*EMB];  // [b,h,l,d]
__device__ __align__(16) __nv_bfloat16 g_ctxh[NTOK*EMB], g_ctxl[NTOK*EMB];
__device__ float g_att [NTOK*EMB];
__device__ float g_post[NTOK*EMB];
__device__ __align__(16) __nv_bfloat16 g_ph[NTOK*EMB],  g_pl[NTOK*EMB];
__device__ __align__(16) __nv_bfloat16 g_h1h[NTOK*FFN], g_h1l[NTOK*FFN];
__device__ float g_ff  [NTOK*EMB];

// ================= helpers ==================================================
__device__ __forceinline__ uint32_t smem_u32(const void* p) {
    uint32_t a;
    asm("{ .reg .u64 t; cvta.to.shared.u64 t, %1; cvt.u32.u64 %0, t; }" : "=r"(a) : "l"(p));
    return a;
}
__device__ __forceinline__ void cpa16(uint32_t s, const void* g) {
    asm volatile("cp.async.cg.shared.global [%0], [%1], 16;" :: "r"(s), "l"(g) : "memory");
}
#define CP_COMMIT() asm volatile("cp.async.commit_group;" ::: "memory")

#define LDSM4(r, addr) \
    asm volatile("ldmatrix.sync.aligned.m8n8.x4.shared.b16 {%0,%1,%2,%3}, [%4];" \
        : "=r"((r)[0]), "=r"((r)[1]), "=r"((r)[2]), "=r"((r)[3]) : "r"(addr))

#define MMA16816(c, a, b0, b1) \
    asm volatile("mma.sync.aligned.m16n8k16.row.col.f32.bf16.bf16.f32 " \
        "{%0,%1,%2,%3}, {%4,%5,%6,%7}, {%8,%9}, {%0,%1,%2,%3};" \
        : "+f"((c)[0]), "+f"((c)[1]), "+f"((c)[2]), "+f"((c)[3]) \
        : "r"((a)[0]), "r"((a)[1]), "r"((a)[2]), "r"((a)[3]), "r"(b0), "r"(b1))

__device__ __forceinline__ void split2(float v0, float v1, uint32_t& hi, uint32_t& lo) {
    __nv_bfloat162 hp, lp;
    hp.x = __float2bfloat16(v0); hp.y = __float2bfloat16(v1);
    lp.x = __float2bfloat16(v0 - __bfloat162float(hp.x));
    lp.y = __float2bfloat16(v1 - __bfloat162float(hp.y));
    hi = *(uint32_t*)&hp; lo = *(uint32_t*)&lp;
}

// ================= mma.sync split-bf16 GEMM =================================
// C[M,N] = A[M,K] @ Bt[N,K]^T (+bias, epilogue). A,B given as (hi,lo) bf16 pairs.
// CTA tile 128x256, 8 warps (2x4) x warp tile 64x64, K-chunk 64, 2-stage pipe.
#define EPI_PLAIN    0
#define EPI_RELU_HL  1
#define EPI_QV       2

#define ROWB  144
#define MAT_A (128*ROWB)              // 18432
#define MAT_B (256*ROWB)              // 36864
#define STAGE (2*MAT_A + 2*MAT_B)     // 110592
#define GSMEM (2*STAGE)               // 221184

__device__ __forceinline__ void g_load_chunk(uint32_t stg,
        const char* ah, const char* al, const char* bh, const char* bl,
        size_t rowb, size_t ko, int t)
{
#pragma unroll
    for (int i = t; i < 2048; i += 256) {          // A: 2 mats x 128 rows x 8x16B
        int mat = i >> 10, idx = i & 1023, row = idx >> 3, c = idx & 7;
        cpa16(stg + mat*MAT_A + row*ROWB + c*16,
              (mat ? al : ah) + (size_t)row*rowb + ko + c*16);
    }
#pragma unroll
    for (int i = t; i < 4096; i += 256) {          // B: 2 mats x 256 rows x 8x16B
        int mat = i >> 11, idx = i & 2047, row = idx >> 3, c = idx & 7;
        cpa16(stg + 2*MAT_A + mat*MAT_B + row*ROWB + c*16,
              (mat ? bl : bh) + (size_t)row*rowb + ko + c*16);
    }
    CP_COMMIT();
}

template<int EPI>
__global__ __launch_bounds__(256, 1)
void mma_gemm(const __nv_bfloat16* __restrict__ Ah, const __nv_bfloat16* __restrict__ Al,
              const __nv_bfloat16* __restrict__ Bh, const __nv_bfloat16* __restrict__ Bl,
              const float* __restrict__ bias, const float* __restrict__ bias2,
              float* __restrict__ Cf, __nv_bfloat16* __restrict__ Ch, __nv_bfloat16* __restrict__ Cl,
              __nv_bfloat16* __restrict__ C2h, __nv_bfloat16* __restrict__ C2l,
              int M, int N, int K)
{
    extern __shared__ char smem[];
    const uint32_t sb = smem_u32(smem);
    const int t = threadIdx.x, wid = t >> 5, lane = t & 31;
    const int bm = blockIdx.y, bn = blockIdx.x;
    const int wm = wid >> 2, wn = wid & 3;

    const size_t rowb = (size_t)K * 2;
    const char* Abh = (const char*)Ah + (size_t)bm*128*rowb;
    const char* Abl = (const char*)Al + (size_t)bm*128*rowb;
    const char* Bbh = (const char*)Bh + (size_t)bn*256*rowb;
    const char* Bbl = (const char*)Bl + (size_t)bn*256*rowb;

    float acc[4][8][4];
#pragma unroll
    for (int i = 0; i < 4; i++)
#pragma unroll
        for (int j = 0; j < 8; j++)
#pragma unroll
            for (int r = 0; r < 4; r++) acc[i][j][r] = 0.f;

    const int nch = K >> 6;
    g_load_chunk(sb,         Abh, Abl, Bbh, Bbl, rowb, 0,   t);
    g_load_chunk(sb + STAGE, Abh, Abl, Bbh, Bbl, rowb, 128, t);

    const int lr = lane & 15;
    const int lc = (lane >> 4) * 16;

    for (int kc = 0; kc < nch; kc++) {
        const int s = kc & 1;
        const uint32_t stg = sb + s*STAGE;
        if (kc + 1 < nch) asm volatile("cp.async.wait_group 1;" ::: "memory");
        else              asm volatile("cp.async.wait_group 0;" ::: "memory");
        __syncthreads();

        const uint32_t a_h = stg,              a_l = stg + MAT_A;
        const uint32_t b_h = stg + 2*MAT_A,    b_l = stg + 2*MAT_A + MAT_B;

#pragma unroll
        for (int ks = 0; ks < 4; ks++) {
            const uint32_t koff = ks*32 + lc;
            uint32_t ah[4][4], al[4][4];
#pragma unroll
            for (int mt = 0; mt < 4; mt++) {
                const uint32_t ro = (wm*64 + mt*16 + lr)*ROWB + koff;
                LDSM4(ah[mt], a_h + ro);
                LDSM4(al[mt], a_l + ro);
            }
#pragma unroll
            for (int h2 = 0; h2 < 4; h2++) {
                uint32_t bhf[4], blf[4];
                const uint32_t ro = (wn*64 + h2*16 + lr)*ROWB + koff;
                LDSM4(bhf, b_h + ro);
                LDSM4(blf, b_l + ro);
#pragma unroll
                for (int q = 0; q < 2; q++) {
                    const int nt = h2*2 + q;
#pragma unroll
                    for (int mt = 0; mt < 4; mt++) {
                        MMA16816(acc[mt][nt], ah[mt], bhf[q], bhf[2+q]); // hi*hi
                        MMA16816(acc[mt][nt], ah[mt], blf[q], blf[2+q]); // hi*lo
                        MMA16816(acc[mt][nt], al[mt], bhf[q], bhf[2+q]); // lo*hi
                    }
                }
            }
        }
        __syncthreads();
        if (kc + 2 < nch)
            g_load_chunk(stg, Abh, Abl, Bbh, Bbl, rowb, (size_t)(kc + 2)*128, t);
    }

    // ---- epilogue straight from registers
    const int qr = lane >> 2, qc = (lane & 3) * 2;
#pragma unroll
    for (int nt = 0; nt < 8; nt++) {
        const int gc = bn*256 + wn*64 + nt*8 + qc;
#pragma unroll
        for (int mt = 0; mt < 4; mt++) {
            const int gr = bm*128 + wm*64 + mt*16 + qr;
#pragma unroll
            for (int half = 0; half < 2; half++) {
                const int row = gr + half*8;
                if (EPI == EPI_PLAIN) {
                    const float v0 = acc[mt][nt][2*half+0] + bias[gc];
                    const float v1 = acc[mt][nt][2*half+1] + bias[gc+1];
                    *(float2*)(Cf + (size_t)row*N + gc) = make_float2(v0, v1);
                } else if (EPI == EPI_RELU_HL) {
                    const float v0 = fmaxf(acc[mt][nt][2*half+0] + bias[gc],   0.f);
                    const float v1 = fmaxf(acc[mt][nt][2*half+1] + bias[gc+1], 0.f);
                    uint32_t hp, lp;
                    split2(v0, v1, hp, lp);
                    *(uint32_t*)(Ch + (size_t)row*N + gc) = hp;
                    *(uint32_t*)(Cl + (size_t)row*N + gc) = lp;
                } else { // EPI_QV: cols [0,1024) -> Q (scaled 1/8), [1024,2048) -> V
                    const int isv = gc >> 10, hcol = gc & 1023;
                    const float* bp = isv ? bias2 : bias;
                    const float sc = isv ? 1.f : 0.125f;
                    const float v0 = (acc[mt][nt][2*half+0] + bp[hcol])   * sc;
                    const float v1 = (acc[mt][nt][2*half+1] + bp[hcol+1]) * sc;
                    const int h = hcol >> 6, d = hcol & 63;
                    const int b = row >> 11, ltok = row & 2047;
                    const size_t off = ((size_t)(b*HEADS + h)*SEQL + ltok)*DHEAD + d;
                    uint32_t hp, lp;
                    split2(v0, v1, hp, lp);
                    *(uint32_t*)((isv ? C2h : Ch) + off) = hp;
                    *(uint32_t*)((isv ? C2l : Cl) + off) = lp;
                }
            }
        }
    }
}

// ================= conversion kernels =======================================
__global__ __launch_bounds__(256)
void convert_hl(const float4* __restrict__ in, __nv_bfloat16* __restrict__ h,
                __nv_bfloat16* __restrict__ l, int n4)
{
    int i = blockIdx.x*256 + threadIdx.x;
    if (i >= n4) return;
    float4 v = in[i];
    uint32_t h0, l0, h1, l1;
    split2(v.x, v.y, h0, l0);
    split2(v.z, v.w, h1, l1);
    ((uint32_t*)h)[2*i]   = h0; ((uint32_t*)h)[2*i+1] = h1;
    ((uint32_t*)l)[2*i]   = l0; ((uint32_t*)l)[2*i+1] = l1;
}

// W[K][N] fp32 -> Th/Tl[N][K] bf16 (transposed split)
__global__ void conv_transpose(const float* __restrict__ W, __nv_bfloat16* __restrict__ Th,
                               __nv_bfloat16* __restrict__ Tl, int K, int N)
{
    __shared__ float tile[32][33];
    const int n0 = blockIdx.x*32, k0 = blockIdx.y*32;
    const int tx = threadIdx.x, ty = threadIdx.y;
#pragma unroll
    for (int i = ty; i < 32; i += 8)
        tile[i][tx] = W[(size_t)(k0+i)*N + n0 + tx];
    __syncthreads();
#pragma unroll
    for (int i = ty; i < 32; i += 8) {
        float v = tile[tx][i];
        __nv_bfloat16 h = __float2bfloat16(v);
        Th[(size_t)(n0+i)*K + k0 + tx] = h;
        Tl[(size_t)(n0+i)*K + k0 + tx] = __float2bfloat16(v - __bfloat162float(h));
    }
}

// ================= tensor-core flash attention ==============================
#define AROW 144
#define SQ_L (128*AROW)
#define SSTG (2*128*AROW)
#define STG_SZ (4*64*AROW)
#define ATT_SMEM (SSTG + 2*STG_SZ)    // 110592

__global__ __launch_bounds__(256)
void attn_mma(const __nv_bfloat16* __restrict__ Qh, const __nv_bfloat16* __restrict__ Ql,
              const __nv_bfloat16* __restrict__ Vh, const __nv_bfloat16* __restrict__ Vl,
              __nv_bfloat16* __restrict__ ctxh, __nv_bfloat16* __restrict__ ctxl)
{
    extern __shared__ char smem[];
    const uint32_t sb = smem_u32(smem);
    const int t = threadIdx.x, wid = t >> 5, lane = t & 31;
    const int qt = blockIdx.x, bh = blockIdx.y;

    const char* Qbh = (const char*)(Qh + ((size_t)bh*SEQL + qt*128)*DHEAD);
    const char* Qbl = (const char*)(Ql + ((size_t)bh*SEQL + qt*128)*DHEAD);
    const char* Vbh = (const char*)(Vh + (size_t)bh*SEQL*DHEAD);
    const char* Vbl = (const char*)(Vl + (size_t)bh*SEQL*DHEAD);

#pragma unroll
    for (int i = t; i < 1024; i += 256) {
        int r = i >> 3, c = i & 7;
        cpa16(sb + r*AROW + c*16,        Qbh + r*128 + c*16);
        cpa16(sb + SQ_L + r*AROW + c*16, Qbl + r*128 + c*16);
    }
#pragma unroll
    for (int i = t; i < 512; i += 256) {
        int r = i >> 3, c = i & 7;
        cpa16(sb + SSTG + r*AROW + c*16,           Vbh + r*128 + c*16);
        cpa16(sb + SSTG + 64*AROW + r*AROW + c*16, Vbl + r*128 + c*16);
    }
    CP_COMMIT();

    const int lr = lane & 15;
    const int lc = (lane >> 4) * 16;

    uint32_t qfh[4][4], qfl[4][4];
    float m[2] = {-FLT_MAX, -FLT_MAX}, lsum[2] = {0.f, 0.f};
    float o[8][4];
#pragma unroll
    for (int nt = 0; nt < 8; nt++)
#pragma unroll
        for (int r = 0; r < 4; r++) o[nt][r] = 0.f;

    for (int kt = 0; kt < SEQL/64; kt++) {
        const int s = kt & 1;
        const uint32_t stg = sb + SSTG + s*STG_SZ;

        if (kt + 1 < SEQL/64) {
            const uint32_t nstg = sb + SSTG + (1-s)*STG_SZ;
            const char* nh = Vbh + (size_t)(kt+1)*64*128;
            const char* nl = Vbl + (size_t)(kt+1)*64*128;
#pragma unroll
            for (int i = t; i < 512; i += 256) {
                int r = i >> 3, c = i & 7;
                cpa16(nstg + r*AROW + c*16,           nh + r*128 + c*16);
                cpa16(nstg + 64*AROW + r*AROW + c*16, nl + r*128 + c*16);
            }
            CP_COMMIT();
            asm volatile("cp.async.wait_group 1;" ::: "memory");
        } else {
            asm volatile("cp.async.wait_group 0;" ::: "memory");
        }
        __syncthreads();

        // transpose V tile: VS[k][d] -> VT[d][k] (hi & lo)
        {
            const uint32_t vsh = stg, vsl = stg + 64*AROW;
            const uint32_t vth = stg + 2*64*AROW, vtl = stg + 3*64*AROW;
#pragma unroll
            for (int i = t; i < 4096; i += 256) {
                int k = i >> 6, d = i & 63;
                uint16_t a, b2;
                asm volatile("ld.shared.u16 %0, [%1];" : "=h"(a)  : "r"(vsh + k*AROW + d*2));
                asm volatile("ld.shared.u16 %0, [%1];" : "=h"(b2) : "r"(vsl + k*AROW + d*2));
                asm volatile("st.shared.u16 [%0], %1;" :: "r"(vth + d*AROW + k*2), "h"(a));
                asm volatile("st.shared.u16 [%0], %1;" :: "r"(vtl + d*AROW + k*2), "h"(b2));
            }
        }
        __syncthreads();

        if (kt == 0) {
#pragma unroll
            for (int ks = 0; ks < 4; ks++) {
                const uint32_t ro = (wid*16 + lr)*AROW + ks*32 + lc;
                LDSM4(qfh[ks], sb + ro);
                LDSM4(qfl[ks], sb + SQ_L + ro);
            }
        }

        // ---- S = Q @ V^T
        float sc[8][4];
#pragma unroll
        for (int nt = 0; nt < 8; nt++)
#pragma unroll
            for (int r = 0; r < 4; r++) sc[nt][r] = 0.f;

#pragma unroll
        for (int ks = 0; ks < 4; ks++) {
            const uint32_t koff = ks*32 + lc;
#pragma unroll
            for (int h2 = 0; h2 < 4; h2++) {
                uint32_t bvh[4], bvl[4];
                const uint32_t ro = (h2*16 + lr)*AROW + koff;
                LDSM4(bvh, stg + ro);
                LDSM4(bvl, stg + 64*AROW + ro);
#pragma unroll
                for (int q = 0; q < 2; q++) {
                    const int nt = h2*2 + q;
                    MMA16816(sc[nt], qfh[ks], bvh[q], bvh[2+q]);
                    MMA16816(sc[nt], qfh[ks], bvl[q], bvl[2+q]);
                    MMA16816(sc[nt], qfl[ks], bvh[q], bvh[2+q]);
                }
            }
        }

        // ---- online softmax
#pragma unroll
        for (int i = 0; i < 2; i++) {
            float mx = -FLT_MAX;
#pragma unroll
            for (int nt = 0; nt < 8; nt++)
                mx = fmaxf(mx, fmaxf(sc[nt][2*i], sc[nt][2*i+1]));
            mx = fmaxf(mx, __shfl_xor_sync(0xffffffffu, mx, 1));
            mx = fmaxf(mx, __shfl_xor_sync(0xffffffffu, mx, 2));
            const float mnew = fmaxf(m[i], mx);
            const float alpha = __expf(m[i] - mnew);
            float rs = 0.f;
#pragma unroll
            for (int nt = 0; nt < 8; nt++) {
                sc[nt][2*i]   = __expf(sc[nt][2*i]   - mnew);
                sc[nt][2*i+1] = __expf(sc[nt][2*i+1] - mnew);
                rs += sc[nt][2*i] + sc[nt][2*i+1];
            }
            rs += __shfl_xor_sync(0xffffffffu, rs, 1);
            rs += __shfl_xor_sync(0xffffffffu, rs, 2);
            lsum[i] = lsum[i]*alpha + rs;
            m[i] = mnew;
#pragma unroll
            for (int nt = 0; nt < 8; nt++) {
                o[nt][2*i]   *= alpha;
                o[nt][2*i+1] *= alpha;
            }
        }

        // ---- pack P into A-fragments (hi/lo)
        uint32_t aph[4][4], apl[4][4];
#pragma unroll
        for (int k2 = 0; k2 < 4; k2++) {
            split2(sc[2*k2][0],   sc[2*k2][1],   aph[k2][0], apl[k2][0]);
            split2(sc[2*k2][2],   sc[2*k2][3],   aph[k2][1], apl[k2][1]);
            split2(sc[2*k2+1][0], sc[2*k2+1][1], aph[k2][2], apl[k2][2]);
            split2(sc[2*k2+1][2], sc[2*k2+1][3], aph[k2][3], apl[k2][3]);
        }

        // ---- O += P @ V
        const uint32_t vth = stg + 2*64*AROW, vtl = stg + 3*64*AROW;
#pragma unroll
        for (int k2 = 0; k2 < 4; k2++) {
            const uint32_t koff = k2*32 + lc;
#pragma unroll
            for (int h2 = 0; h2 < 4; h2++) {
                uint32_t bth[4], btl[4];
                const uint32_t ro = (h2*16 + lr)*AROW + koff;
                LDSM4(bth, vth + ro);
                LDSM4(btl, vtl + ro);
#pragma unroll
                for (int q = 0; q < 2; q++) {
                    const int nt = h2*2 + q;
                    MMA16816(o[nt], aph[k2], bth[q], bth[2+q]);
                    MMA16816(o[nt], apl[k2], bth[q], bth[2+q]);
                    MMA16816(o[nt], aph[k2], btl[q], btl[2+q]);
                }
            }
        }
        __syncthreads();
    }

    // ---- epilogue
    const int g = lane >> 2, qc = (lane & 3)*2;
    const int b = bh >> 4, h = bh & 15;
#pragma unroll
    for (int i = 0; i < 2; i++) {
        const float inv = 1.f / lsum[i];
        const int ltok = qt*128 + wid*16 + g + i*8;
        const size_t rowoff = (size_t)(b*SEQL + ltok)*EMB + h*DHEAD;
#pragma unroll
        for (int nt = 0; nt < 8; nt++) {
            uint32_t hp, lp;
            split2(o[nt][2*i]*inv, o[nt][2*i+1]*inv, hp, lp);
            *(uint32_t*)(ctxh + rowoff + nt*8 + qc) = hp;
            *(uint32_t*)(ctxl + rowoff + nt*8 + qc) = lp;
        }
    }
}

// ================= fused residual add + LayerNorm ===========================
template<bool HL>
__global__ __launch_bounds__(256)
void add_ln_kernel(const float* __restrict__ a, const float* __restrict__ bres,
                   const float* __restrict__ gamma, const float* __restrict__ beta,
                   float* __restrict__ out,
                   __nv_bfloat16* __restrict__ oh, __nv_bfloat16* __restrict__ ol)
{
    const int row = blockIdx.x;
    const int t = threadIdx.x;
    const int lane = t & 31, wid = t >> 5;

    const float4* ap = (const float4*)(a + (size_t)row * EMB);
    const float4* bp = (const float4*)(bres + (size_t)row * EMB);
    float4 av = ap[t], bv = bp[t];
    float v0 = av.x + bv.x, v1 = av.y + bv.y, v2 = av.z + bv.z, v3 = av.w + bv.w;

    float sum = v0 + v1 + v2 + v3;
    float sq  = v0*v0 + v1*v1 + v2*v2 + v3*v3;
#pragma unroll
    for (int off = 16; off >= 1; off >>= 1) {
        sum += __shfl_xor_sync(0xffffffffu, sum, off);
        sq  += __shfl_xor_sync(0xffffffffu, sq, off);
    }
    __shared__ float ssum[8], ssq[8], s_mean, s_rstd;
    if (lane == 0) { ssum[wid] = sum; ssq[wid] = sq; }
    __syncthreads();
    if (t == 0) {
        float S = 0.f, Q = 0.f;
#pragma unroll
        for (int w = 0; w < 8; w++) { S += ssum[w]; Q += ssq[w]; }
        float mean = S * (1.f/EMB);
        float var  = Q * (1.f/EMB) - mean*mean;
        s_mean = mean;
        s_rstd = rsqrtf(var + LN_EPS);
    }
    __syncthreads();
    const float mean = s_mean, rstd = s_rstd;

    float4 g = ((const float4*)gamma)[t], bt = ((const float4*)beta)[t];
    float4 r;
    r.x = (v0 - mean) * rstd * g.x + bt.x;
    r.y = (v1 - mean) * rstd * g.y + bt.y;
    r.z = (v2 - mean) * rstd * g.z + bt.z;
    r.w = (v3 - mean) * rstd * g.w + bt.w;
    ((float4*)(out + (size_t)row * EMB))[t] = r;

    if (HL) {
        size_t off = (size_t)row * EMB + 4*t;
        uint32_t h0, l0, h1, l1;
        split2(r.x, r.y, h0, l0);
        split2(r.z, r.w, h1, l1);
        *(uint32_t*)(oh + off)     = h0;
        *(uint32_t*)(oh + off + 2) = h1;
        *(uint32_t*)(ol + off)     = l0;
        *(uint32_t*)(ol + off + 2) = l1;
    }
}

// ================= launch ====================================================
extern "C" void kernel_launch(void* const* d_in, const int* in_sizes, int n_in,
                              void* d_out, int out_size)
{
    const float* x   = (const float*)d_in[0];
    const float* Wq  = (const float*)d_in[1];
    const float* bq  = (const float*)d_in[2];
    // d_in[3], d_in[4] = Wk, bk: dead code in the reference (scores use Q@V^T)
    const float* Wv  = (const float*)d_in[5];
    const float* bv  = (const float*)d_in[6];
    const float* Wo  = (const float*)d_in[7];
    const float* bo  = (const float*)d_in[8];
    const float* g1  = (const float*)d_in[9];
    const float* b1  = (const float*)d_in[10];
    const float* W1  = (const float*)d_in[11];
    const float* bf1 = (const float*)d_in[12];
    const float* W2  = (const float*)d_in[13];
    const float* bf2 = (const float*)d_in[14];
    const float* g2  = (const float*)d_in[15];
    const float* b2  = (const float*)d_in[16];
    float* out = (float*)d_out;

    __nv_bfloat16 *xh,*xl,*Wqvh,*Wqvl,*Woh,*Wol,*W1h,*W1l,*W2h,*W2l;
    __nv_bfloat16 *Qbh,*Qbl,*Vbh,*Vbl,*ctxh,*ctxl,*ph,*pl,*h1h,*h1l;
    float *attp,*postp,*ffp;
    cudaGetSymbolAddress((void**)&xh,  g_xh);  cudaGetSymbolAddress((void**)&xl,  g_xl);
    cudaGetSymbolAddress((void**)&Wqvh,g_Wqvh);cudaGetSymbolAddress((void**)&Wqvl,g_Wqvl);
    cudaGetSymbolAddress((void**)&Woh, g_Woh); cudaGetSymbolAddress((void**)&Wol, g_Wol);
    cudaGetSymbolAddress((void**)&W1h, g_W1h); cudaGetSymbolAddress((void**)&W1l, g_W1l);
    cudaGetSymbolAddress((void**)&W2h, g_W2h); cudaGetSymbolAddress((void**)&W2l, g_W2l);
    cudaGetSymbolAddress((void**)&Qbh, g_Qh);  cudaGetSymbolAddress((void**)&Qbl, g_Ql);
    cudaGetSymbolAddress((void**)&Vbh, g_Vh);  cudaGetSymbolAddress((void**)&Vbl, g_Vl);
    cudaGetSymbolAddress((void**)&ctxh,g_ctxh);cudaGetSymbolAddress((void**)&ctxl,g_ctxl);
    cudaGetSymbolAddress((void**)&attp,g_att); cudaGetSymbolAddress((void**)&postp,g_post);
    cudaGetSymbolAddress((void**)&ph,  g_ph);  cudaGetSymbolAddress((void**)&pl,  g_pl);
    cudaGetSymbolAddress((void**)&h1h, g_h1h); cudaGetSymbolAddress((void**)&h1l, g_h1l);
    cudaGetSymbolAddress((void**)&ffp, g_ff);

    cudaFuncSetAttribute(mma_gemm<EPI_PLAIN>,   cudaFuncAttributeMaxDynamicSharedMemorySize, GSMEM);
    cudaFuncSetAttribute(mma_gemm<EPI_RELU_HL>, cudaFuncAttributeMaxDynamicSharedMemorySize, GSMEM);
    cudaFuncSetAttribute(mma_gemm<EPI_QV>,      cudaFuncAttributeMaxDynamicSharedMemorySize, GSMEM);
    cudaFuncSetAttribute(attn_mma, cudaFuncAttributeMaxDynamicSharedMemorySize, ATT_SMEM);

    dim3 blk(256);
    dim3 tblk(32, 8);

    // input / weight conversion (hi/lo split; weights transposed to [N][K])
    convert_hl<<<NTOK*EMB/4/256, blk>>>((const float4*)x, xh, xl, NTOK*EMB/4);
    conv_transpose<<<dim3(EMB/32, EMB/32), tblk>>>(Wq, Wqvh, Wqvl, EMB, EMB);
    conv_transpose<<<dim3(EMB/32, EMB/32), tblk>>>(Wv, Wqvh + (size_t)EMB*EMB,
                                                   Wqvl + (size_t)EMB*EMB, EMB, EMB);
    conv_transpose<<<dim3(EMB/32, EMB/32), tblk>>>(Wo, Woh, Wol, EMB, EMB);
    conv_transpose<<<dim3(FFN/32, EMB/32), tblk>>>(W1, W1h, W1l, EMB, FFN);
    conv_transpose<<<dim3(EMB/32, FFN/32), tblk>>>(W2, W2h, W2l, FFN, EMB);

    // fused Q+V projection -> [b,h,l,d] bf16 hi/lo (Q pre-scaled by 1/8)
    mma_gemm<EPI_QV><<<dim3(2*EMB/256, NTOK/128), blk, GSMEM>>>(
        xh, xl, Wqvh, Wqvl, bq, bv, nullptr, Qbh, Qbl, Vbh, Vbl, NTOK, 2*EMB, EMB);

    // tensor-core flash attention -> ctx hi/lo [tok][E]
    attn_mma<<<dim3(SEQL/128, BATCH*HEADS), blk, ATT_SMEM>>>(Qbh, Qbl, Vbh, Vbl, ctxh, ctxl);

    // output projection -> att fp32
    mma_gemm<EPI_PLAIN><<<dim3(EMB/256, NTOK/128), blk, GSMEM>>>(
        ctxh, ctxl, Woh, Wol, bo, nullptr, attp, nullptr, nullptr, nullptr, nullptr,
        NTOK, EMB, EMB);

    // post = LN(x + att), plus hi/lo for FFN input
    add_ln_kernel<true><<<NTOK, blk>>>(x, attp, g1, b1, postp, ph, pl);

    // FFN
    mma_gemm<EPI_RELU_HL><<<dim3(FFN/256, NTOK/128), blk, GSMEM>>>(
        ph, pl, W1h, W1l, bf1, nullptr, nullptr, h1h, h1l, nullptr, nullptr,
        NTOK, FFN, EMB);
    mma_gemm<EPI_PLAIN><<<dim3(EMB/256, NTOK/128), blk, GSMEM>>>(
        h1h, h1l, W2h, W2l, bf2, nullptr, ffp, nullptr, nullptr, nullptr, nullptr,
        NTOK, EMB, FFN);

    // out = LN(post + ff)
    add_ln_kernel<false><<<NTOK, blk>>>(postp, ffp, g2, b2, out, nullptr, nullptr);
}

// round 14
// speedup vs baseline: 1.0024x; 1.0024x over previous
#include <cuda_runtime.h>
#include <cuda_bf16.h>
#include <math.h>
#include <float.h>
#include <stdint.h>

// Problem constants
#define BATCH 2
#define SEQL  2048
#define EMB   1024
#define HEADS 16
#define DHEAD 64
#define FFN   4096
#define NTOK  (BATCH*SEQL)   // 4096
#define LN_EPS 1e-5f

// ================= scratch (device globals; no allocation allowed) ==========
__device__ __align__(16) __nv_bfloat16 g_xh [NTOK*EMB], g_xl [NTOK*EMB];
__device__ __align__(16) __nv_bfloat16 g_Wqvh[2*EMB*EMB], g_Wqvl[2*EMB*EMB]; // [N=2048][K=1024]
__device__ __align__(16) __nv_bfloat16 g_Woh[EMB*EMB],  g_Wol[EMB*EMB];
__device__ __align__(16) __nv_bfloat16 g_W1h[EMB*FFN],  g_W1l[EMB*FFN];   // [N=FFN][K=EMB]
__device__ __align__(16) __nv_bfloat16 g_W2h[EMB*FFN],  g_W2l[EMB*FFN];   // [N=EMB][K=FFN]
__device__ __align__(16) __nv_bfloat16 g_Qh [NTOK*EMB], g_Ql [NTOK*EMB];  // [b,h,l,d], pre-scaled 1/8
__device__ __align__(16) __nv_bfloat16 g_Vh [NTOK*EMB], g_Vl [NTOK*EMB];  // [b,h,l,d]
__device__ __align__(16) __nv_bfloat16 g_ctxh[NTOK*EMB], g_ctxl[NTOK*EMB];
__device__ float g_att [NTOK*EMB];
__device__ float g_post[NTOK*EMB];
__device__ __align__(16) __nv_bfloat16 g_ph[NTOK*EMB],  g_pl[NTOK*EMB];
__device__ __align__(16) __nv_bfloat16 g_h1h[NTOK*FFN], g_h1l[NTOK*FFN];
__device__ float g_ff  [NTOK*EMB];

// ================= helpers ==================================================
__device__ __forceinline__ uint32_t smem_u32(const void* p) {
    uint32_t a;
    asm("{ .reg .u64 t; cvta.to.shared.u64 t, %1; cvt.u32.u64 %0, t; }" : "=r"(a) : "l"(p));
    return a;
}
__device__ __forceinline__ void cpa16(uint32_t s, const void* g) {
    asm volatile("cp.async.cg.shared.global [%0], [%1], 16;" :: "r"(s), "l"(g) : "memory");
}
#define CP_COMMIT() asm volatile("cp.async.commit_group;" ::: "memory")

#define LDSM4(r, addr) \
    asm volatile("ldmatrix.sync.aligned.m8n8.x4.shared.b16 {%0,%1,%2,%3}, [%4];" \
        : "=r"((r)[0]), "=r"((r)[1]), "=r"((r)[2]), "=r"((r)[3]) : "r"(addr))

#define MMA16816(c, a, b0, b1) \
    asm volatile("mma.sync.aligned.m16n8k16.row.col.f32.bf16.bf16.f32 " \
        "{%0,%1,%2,%3}, {%4,%5,%6,%7}, {%8,%9}, {%0,%1,%2,%3};" \
        : "+f"((c)[0]), "+f"((c)[1]), "+f"((c)[2]), "+f"((c)[3]) \
        : "r"((a)[0]), "r"((a)[1]), "r"((a)[2]), "r"((a)[3]), "r"(b0), "r"(b1))

__device__ __forceinline__ void split2(float v0, float v1, uint32_t& hi, uint32_t& lo) {
    __nv_bfloat162 hp, lp;
    hp.x = __float2bfloat16(v0); hp.y = __float2bfloat16(v1);
    lp.x = __float2bfloat16(v0 - __bfloat162float(hp.x));
    lp.y = __float2bfloat16(v1 - __bfloat162float(hp.y));
    hi = *(uint32_t*)&hp; lo = *(uint32_t*)&lp;
}

// ================= mma.sync split-bf16 GEMM =================================
// C[M,N] = A[M,K] @ Bt[N,K]^T (+bias, epilogue). A,B given as (hi,lo) bf16 pairs.
// CTA tile 128x256, 8 warps (2x4) x warp tile 64x64, K-chunk 64, 2-stage pipe.
#define EPI_PLAIN    0
#define EPI_RELU_HL  1
#define EPI_QV       2

#define ROWB  144
#define MAT_A (128*ROWB)              // 18432
#define MAT_B (256*ROWB)              // 36864
#define STAGE (2*MAT_A + 2*MAT_B)     // 110592
#define GSMEM (2*STAGE)               // 221184

__device__ __forceinline__ void g_load_chunk(uint32_t stg,
        const char* ah, const char* al, const char* bh, const char* bl,
        size_t rowb, size_t ko, int t)
{
#pragma unroll
    for (int i = t; i < 2048; i += 256) {          // A: 2 mats x 128 rows x 8x16B
        int mat = i >> 10, idx = i & 1023, row = idx >> 3, c = idx & 7;
        cpa16(stg + mat*MAT_A + row*ROWB + c*16,
              (mat ? al : ah) + (size_t)row*rowb + ko + c*16);
    }
#pragma unroll
    for (int i = t; i < 4096; i += 256) {          // B: 2 mats x 256 rows x 8x16B
        int mat = i >> 11, idx = i & 2047, row = idx >> 3, c = idx & 7;
        cpa16(stg + 2*MAT_A + mat*MAT_B + row*ROWB + c*16,
              (mat ? bl : bh) + (size_t)row*rowb + ko + c*16);
    }
    CP_COMMIT();
}

template<int EPI>
__global__ __launch_bounds__(256, 1)
void mma_gemm(const __nv_bfloat16* __restrict__ Ah, const __nv_bfloat16* __restrict__ Al,
              const __nv_bfloat16* __restrict__ Bh, const __nv_bfloat16* __restrict__ Bl,
              const float* __restrict__ bias, const float* __restrict__ bias2,
              float* __restrict__ Cf, __nv_bfloat16* __restrict__ Ch, __nv_bfloat16* __restrict__ Cl,
              __nv_bfloat16* __restrict__ C2h, __nv_bfloat16* __restrict__ C2l,
              int M, int N, int K)
{
    extern __shared__ char smem[];
    const uint32_t sb = smem_u32(smem);
    const int t = threadIdx.x, wid = t >> 5, lane = t & 31;
    const int bm = blockIdx.y, bn = blockIdx.x;
    const int wm = wid >> 2, wn = wid & 3;

    const size_t rowb = (size_t)K * 2;
    const char* Abh = (const char*)Ah + (size_t)bm*128*rowb;
    const char* Abl = (const char*)Al + (size_t)bm*128*rowb;
    const char* Bbh = (const char*)Bh + (size_t)bn*256*rowb;
    const char* Bbl = (const char*)Bl + (size_t)bn*256*rowb;

    float acc[4][8][4];
#pragma unroll
    for (int i = 0; i < 4; i++)
#pragma unroll
        for (int j = 0; j < 8; j++)
#pragma unroll
            for (int r = 0; r < 4; r++) acc[i][j][r] = 0.f;

    const int nch = K >> 6;
    g_load_chunk(sb,         Abh, Abl, Bbh, Bbl, rowb, 0,   t);
    g_load_chunk(sb + STAGE, Abh, Abl, Bbh, Bbl, rowb, 128, t);

    const int lr = lane & 15;
    const int lc = (lane >> 4) * 16;

    for (int kc = 0; kc < nch; kc++) {
        const int s = kc & 1;
        const uint32_t stg = sb + s*STAGE;
        if (kc + 1 < nch) asm volatile("cp.async.wait_group 1;" ::: "memory");
        else              asm volatile("cp.async.wait_group 0;" ::: "memory");
        __syncthreads();

        const uint32_t a_h = stg,              a_l = stg + MAT_A;
        const uint32_t b_h = stg + 2*MAT_A,    b_l = stg + 2*MAT_A + MAT_B;

#pragma unroll
        for (int ks = 0; ks < 4; ks++) {
            const uint32_t koff = ks*32 + lc;
            uint32_t ah[4][4], al[4][4];
#pragma unroll
            for (int mt = 0; mt < 4; mt++) {
                const uint32_t ro = (wm*64 + mt*16 + lr)*ROWB + koff;
                LDSM4(ah[mt], a_h + ro);
                LDSM4(al[mt], a_l + ro);
            }
#pragma unroll
            for (int h2 = 0; h2 < 4; h2++) {
                uint32_t bhf[4], blf[4];
                const uint32_t ro = (wn*64 + h2*16 + lr)*ROWB + koff;
                LDSM4(bhf, b_h + ro);
                LDSM4(blf, b_l + ro);
#pragma unroll
                for (int q = 0; q < 2; q++) {
                    const int nt = h2*2 + q;
#pragma unroll
                    for (int mt = 0; mt < 4; mt++) {
                        MMA16816(acc[mt][nt], ah[mt], bhf[q], bhf[2+q]); // hi*hi
                        MMA16816(acc[mt][nt], ah[mt], blf[q], blf[2+q]); // hi*lo
                        MMA16816(acc[mt][nt], al[mt], bhf[q], bhf[2+q]); // lo*hi
                    }
                }
            }
        }
        __syncthreads();
        if (kc + 2 < nch)
            g_load_chunk(stg, Abh, Abl, Bbh, Bbl, rowb, (size_t)(kc + 2)*128, t);
    }

    // ---- epilogue straight from registers
    const int qr = lane >> 2, qc = (lane & 3) * 2;
#pragma unroll
    for (int nt = 0; nt < 8; nt++) {
        const int gc = bn*256 + wn*64 + nt*8 + qc;
#pragma unroll
        for (int mt = 0; mt < 4; mt++) {
            const int gr = bm*128 + wm*64 + mt*16 + qr;
#pragma unroll
            for (int half = 0; half < 2; half++) {
                const int row = gr + half*8;
                if (EPI == EPI_PLAIN) {
                    const float v0 = acc[mt][nt][2*half+0] + bias[gc];
                    const float v1 = acc[mt][nt][2*half+1] + bias[gc+1];
                    *(float2*)(Cf + (size_t)row*N + gc) = make_float2(v0, v1);
                } else if (EPI == EPI_RELU_HL) {
                    const float v0 = fmaxf(acc[mt][nt][2*half+0] + bias[gc],   0.f);
                    const float v1 = fmaxf(acc[mt][nt][2*half+1] + bias[gc+1], 0.f);
                    uint32_t hp, lp;
                    split2(v0, v1, hp, lp);
                    *(uint32_t*)(Ch + (size_t)row*N + gc) = hp;
                    *(uint32_t*)(Cl + (size_t)row*N + gc) = lp;
                } else { // EPI_QV: cols [0,1024) -> Q (scaled 1/8), [1024,2048) -> V
                    const int isv = gc >> 10, hcol = gc & 1023;
                    const float* bp = isv ? bias2 : bias;
                    const float sc = isv ? 1.f : 0.125f;
                    const float v0 = (acc[mt][nt][2*half+0] + bp[hcol])   * sc;
                    const float v1 = (acc[mt][nt][2*half+1] + bp[hcol+1]) * sc;
                    const int h = hcol >> 6, d = hcol & 63;
                    const int b = row >> 11, ltok = row & 2047;
                    const size_t off = ((size_t)(b*HEADS + h)*SEQL + ltok)*DHEAD + d;
                    uint32_t hp, lp;
                    split2(v0, v1, hp, lp);
                    *(uint32_t*)((isv ? C2h : Ch) + off) = hp;
                    *(uint32_t*)((isv ? C2l : Cl) + off) = lp;
                }
            }
        }
    }
}

// ================= conversion kernels =======================================
__global__ __launch_bounds__(256)
void convert_hl(const float4* __restrict__ in, __nv_bfloat16* __restrict__ h,
                __nv_bfloat16* __restrict__ l, int n4)
{
    int i = blockIdx.x*256 + threadIdx.x;
    if (i >= n4) return;
    float4 v = in[i];
    uint32_t h0, l0, h1, l1;
    split2(v.x, v.y, h0, l0);
    split2(v.z, v.w, h1, l1);
    ((uint32_t*)h)[2*i]   = h0; ((uint32_t*)h)[2*i+1] = h1;
    ((uint32_t*)l)[2*i]   = l0; ((uint32_t*)l)[2*i+1] = l1;
}

// W[K][N] fp32 -> Th/Tl[N][K] bf16 (transposed split)
__global__ void conv_transpose(const float* __restrict__ W, __nv_bfloat16* __restrict__ Th,
                               __nv_bfloat16* __restrict__ Tl, int K, int N)
{
    __shared__ float tile[32][33];
    const int n0 = blockIdx.x*32, k0 = blockIdx.y*32;
    const int tx = threadIdx.x, ty = threadIdx.y;
#pragma unroll
    for (int i = ty; i < 32; i += 8)
        tile[i][tx] = W[(size_t)(k0+i)*N + n0 + tx];
    __syncthreads();
#pragma unroll
    for (int i = ty; i < 32; i += 8) {
        float v = tile[tx][i];
        __nv_bfloat16 h = __float2bfloat16(v);
        Th[(size_t)(n0+i)*K + k0 + tx] = h;
        Tl[(size_t)(n0+i)*K + k0 + tx] = __float2bfloat16(v - __bfloat162float(h));
    }
}

// ================= tensor-core flash attention ==============================
#define AROW 144
#define SQ_L (128*AROW)
#define SSTG (2*128*AROW)
#define STG_SZ (4*64*AROW)
#define ATT_SMEM (SSTG + 2*STG_SZ)    // 110592

__global__ __launch_bounds__(256)
void attn_mma(const __nv_bfloat16* __restrict__ Qh, const __nv_bfloat16* __restrict__ Ql,
              const __nv_bfloat16* __restrict__ Vh, const __nv_bfloat16* __restrict__ Vl,
              __nv_bfloat16* __restrict__ ctxh, __nv_bfloat16* __restrict__ ctxl)
{
    extern __shared__ char smem[];
    const uint32_t sb = smem_u32(smem);
    const int t = threadIdx.x, wid = t >> 5, lane = t & 31;
    const int qt = blockIdx.x, bh = blockIdx.y;

    const char* Qbh = (const char*)(Qh + ((size_t)bh*SEQL + qt*128)*DHEAD);
    const char* Qbl = (const char*)(Ql + ((size_t)bh*SEQL + qt*128)*DHEAD);
    const char* Vbh = (const char*)(Vh + (size_t)bh*SEQL*DHEAD);
    const char* Vbl = (const char*)(Vl + (size_t)bh*SEQL*DHEAD);

#pragma unroll
    for (int i = t; i < 1024; i += 256) {
        int r = i >> 3, c = i & 7;
        cpa16(sb + r*AROW + c*16,        Qbh + r*128 + c*16);
        cpa16(sb + SQ_L + r*AROW + c*16, Qbl + r*128 + c*16);
    }
#pragma unroll
    for (int i = t; i < 512; i += 256) {
        int r = i >> 3, c = i & 7;
        cpa16(sb + SSTG + r*AROW + c*16,           Vbh + r*128 + c*16);
        cpa16(sb + SSTG + 64*AROW + r*AROW + c*16, Vbl + r*128 + c*16);
    }
    CP_COMMIT();

    const int lr = lane & 15;
    const int lc = (lane >> 4) * 16;

    uint32_t qfh[4][4], qfl[4][4];
    float m[2] = {-FLT_MAX, -FLT_MAX}, lsum[2] = {0.f, 0.f};
    float o[8][4];
#pragma unroll
    for (int nt = 0; nt < 8; nt++)
#pragma unroll
        for (int r = 0; r < 4; r++) o[nt][r] = 0.f;

    for (int kt = 0; kt < SEQL/64; kt++) {
        const int s = kt & 1;
        const uint32_t stg = sb + SSTG + s*STG_SZ;

        if (kt + 1 < SEQL/64) {
            const uint32_t nstg = sb + SSTG + (1-s)*STG_SZ;
            const char* nh = Vbh + (size_t)(kt+1)*64*128;
            const char* nl = Vbl + (size_t)(kt+1)*64*128;
#pragma unroll
            for (int i = t; i < 512; i += 256) {
                int r = i >> 3, c = i & 7;
                cpa16(nstg + r*AROW + c*16,           nh + r*128 + c*16);
                cpa16(nstg + 64*AROW + r*AROW + c*16, nl + r*128 + c*16);
            }
            CP_COMMIT();
            asm volatile("cp.async.wait_group 1;" ::: "memory");
        } else {
            asm volatile("cp.async.wait_group 0;" ::: "memory");
        }
        __syncthreads();

        // transpose V tile: VS[k][d] -> VT[d][k] (hi & lo)
        {
            const uint32_t vsh = stg, vsl = stg + 64*AROW;
            const uint32_t vth = stg + 2*64*AROW, vtl = stg + 3*64*AROW;
#pragma unroll
            for (int i = t; i < 4096; i += 256) {
                int k = i >> 6, d = i & 63;
                uint16_t a, b2;
                asm volatile("ld.shared.u16 %0, [%1];" : "=h"(a)  : "r"(vsh + k*AROW + d*2));
                asm volatile("ld.shared.u16 %0, [%1];" : "=h"(b2) : "r"(vsl + k*AROW + d*2));
                asm volatile("st.shared.u16 [%0], %1;" :: "r"(vth + d*AROW + k*2), "h"(a));
                asm volatile("st.shared.u16 [%0], %1;" :: "r"(vtl + d*AROW + k*2), "h"(b2));
            }
        }
        __syncthreads();

        if (kt == 0) {
#pragma unroll
            for (int ks = 0; ks < 4; ks++) {
                const uint32_t ro = (wid*16 + lr)*AROW + ks*32 + lc;
                LDSM4(qfh[ks], sb + ro);
                LDSM4(qfl[ks], sb + SQ_L + ro);
            }
        }

        // ---- S = Q @ V^T
        float sc[8][4];
#pragma unroll
        for (int nt = 0; nt < 8; nt++)
#pragma unroll
            for (int r = 0; r < 4; r++) sc[nt][r] = 0.f;

#pragma unroll
        for (int ks = 0; ks < 4; ks++) {
            const uint32_t koff = ks*32 + lc;
#pragma unroll
            for (int h2 = 0; h2 < 4; h2++) {
                uint32_t bvh[4], bvl[4];
                const uint32_t ro = (h2*16 + lr)*AROW + koff;
                LDSM4(bvh, stg + ro);
                LDSM4(bvl, stg + 64*AROW + ro);
#pragma unroll
                for (int q = 0; q < 2; q++) {
                    const int nt = h2*2 + q;
                    MMA16816(sc[nt], qfh[ks], bvh[q], bvh[2+q]);
                    MMA16816(sc[nt], qfh[ks], bvl[q], bvl[2+q]);
                    MMA16816(sc[nt], qfl[ks], bvh[q], bvh[2+q]);
                }
            }
        }

        // ---- online softmax
#pragma unroll
        for (int i = 0; i < 2; i++) {
            float mx = -FLT_MAX;
#pragma unroll
            for (int nt = 0; nt < 8; nt++)
                mx = fmaxf(mx, fmaxf(sc[nt][2*i], sc[nt][2*i+1]));
            mx = fmaxf(mx, __shfl_xor_sync(0xffffffffu, mx, 1));
            mx = fmaxf(mx, __shfl_xor_sync(0xffffffffu, mx, 2));
            const float mnew = fmaxf(m[i], mx);
            const float alpha = __expf(m[i] - mnew);
            float rs = 0.f;
#pragma unroll
            for (int nt = 0; nt < 8; nt++) {
                sc[nt][2*i]   = __expf(sc[nt][2*i]   - mnew);
                sc[nt][2*i+1] = __expf(sc[nt][2*i+1] - mnew);
                rs += sc[nt][2*i] + sc[nt][2*i+1];
            }
            rs += __shfl_xor_sync(0xffffffffu, rs, 1);
            rs += __shfl_xor_sync(0xffffffffu, rs, 2);
            lsum[i] = lsum[i]*alpha + rs;
            m[i] = mnew;
#pragma unroll
            for (int nt = 0; nt < 8; nt++) {
                o[nt][2*i]   *= alpha;
                o[nt][2*i+1] *= alpha;
            }
        }

        // ---- pack P into A-fragments (hi/lo)
        uint32_t aph[4][4], apl[4][4];
#pragma unroll
        for (int k2 = 0; k2 < 4; k2++) {
            split2(sc[2*k2][0],   sc[2*k2][1],   aph[k2][0], apl[k2][0]);
            split2(sc[2*k2][2],   sc[2*k2][3],   aph[k2][1], apl[k2][1]);
            split2(sc[2*k2+1][0], sc[2*k2+1][1], aph[k2][2], apl[k2][2]);
            split2(sc[2*k2+1][2], sc[2*k2+1][3], aph[k2][3], apl[k2][3]);
        }

        // ---- O += P @ V
        const uint32_t vth = stg + 2*64*AROW, vtl = stg + 3*64*AROW;
#pragma unroll
        for (int k2 = 0; k2 < 4; k2++) {
            const uint32_t koff = k2*32 + lc;
#pragma unroll
            for (int h2 = 0; h2 < 4; h2++) {
                uint32_t bth[4], btl[4];
                const uint32_t ro = (h2*16 + lr)*AROW + koff;
                LDSM4(bth, vth + ro);
                LDSM4(btl, vtl + ro);
#pragma unroll
                for (int q = 0; q < 2; q++) {
                    const int nt = h2*2 + q;
                    MMA16816(o[nt], aph[k2], bth[q], bth[2+q]);
                    MMA16816(o[nt], apl[k2], bth[q], bth[2+q]);
                    MMA16816(o[nt], aph[k2], btl[q], btl[2+q]);
                }
            }
        }
        __syncthreads();
    }

    // ---- epilogue
    const int g = lane >> 2, qc = (lane & 3)*2;
    const int b = bh >> 4, h = bh & 15;
#pragma unroll
    for (int i = 0; i < 2; i++) {
        const float inv = 1.f / lsum[i];
        const int ltok = qt*128 + wid*16 + g + i*8;
        const size_t rowoff = (size_t)(b*SEQL + ltok)*EMB + h*DHEAD;
#pragma unroll
        for (int nt = 0; nt < 8; nt++) {
            uint32_t hp, lp;
            split2(o[nt][2*i]*inv, o[nt][2*i+1]*inv, hp, lp);
            *(uint32_t*)(ctxh + rowoff + nt*8 + qc) = hp;
            *(uint32_t*)(ctxl + rowoff + nt*8 + qc) = lp;
        }
    }
}

// ================= fused residual add + LayerNorm ===========================
template<bool HL>
__global__ __launch_bounds__(256)
void add_ln_kernel(const float* __restrict__ a, const float* __restrict__ bres,
                   const float* __restrict__ gamma, const float* __restrict__ beta,
                   float* __restrict__ out,
                   __nv_bfloat16* __restrict__ oh, __nv_bfloat16* __restrict__ ol)
{
    const int row = blockIdx.x;
    const int t = threadIdx.x;
    const int lane = t & 31, wid = t >> 5;

    const float4* ap = (const float4*)(a + (size_t)row * EMB);
    const float4* bp = (const float4*)(bres + (size_t)row * EMB);
    float4 av = ap[t], bv = bp[t];
    float v0 = av.x + bv.x, v1 = av.y + bv.y, v2 = av.z + bv.z, v3 = av.w + bv.w;

    float sum = v0 + v1 + v2 + v3;
    float sq  = v0*v0 + v1*v1 + v2*v2 + v3*v3;
#pragma unroll
    for (int off = 16; off >= 1; off >>= 1) {
        sum += __shfl_xor_sync(0xffffffffu, sum, off);
        sq  += __shfl_xor_sync(0xffffffffu, sq, off);
    }
    __shared__ float ssum[8], ssq[8], s_mean, s_rstd;
    if (lane == 0) { ssum[wid] = sum; ssq[wid] = sq; }
    __syncthreads();
    if (t == 0) {
        float S = 0.f, Q = 0.f;
#pragma unroll
        for (int w = 0; w < 8; w++) { S += ssum[w]; Q += ssq[w]; }
        float mean = S * (1.f/EMB);
        float var  = Q * (1.f/EMB) - mean*mean;
        s_mean = mean;
        s_rstd = rsqrtf(var + LN_EPS);
    }
    __syncthreads();
    const float mean = s_mean, rstd = s_rstd;

    float4 g = ((const float4*)gamma)[t], bt = ((const float4*)beta)[t];
    float4 r;
    r.x = (v0 - mean) * rstd * g.x + bt.x;
    r.y = (v1 - mean) * rstd * g.y + bt.y;
    r.z = (v2 - mean) * rstd * g.z + bt.z;
    r.w = (v3 - mean) * rstd * g.w + bt.w;
    ((float4*)(out + (size_t)row * EMB))[t] = r;

    if (HL) {
        size_t off = (size_t)row * EMB + 4*t;
        uint32_t h0, l0, h1, l1;
        split2(r.x, r.y, h0, l0);
        split2(r.z, r.w, h1, l1);
        *(uint32_t*)(oh + off)     = h0;
        *(uint32_t*)(oh + off + 2) = h1;
        *(uint32_t*)(ol + off)     = l0;
        *(uint32_t*)(ol + off + 2) = l1;
    }
}

// ================= launch ====================================================
extern "C" void kernel_launch(void* const* d_in, const int* in_sizes, int n_in,
                              void* d_out, int out_size)
{
    const float* x   = (const float*)d_in[0];
    const float* Wq  = (const float*)d_in[1];
    const float* bq  = (const float*)d_in[2];
    // d_in[3], d_in[4] = Wk, bk: dead code in the reference (scores use Q@V^T)
    const float* Wv  = (const float*)d_in[5];
    const float* bv  = (const float*)d_in[6];
    const float* Wo  = (const float*)d_in[7];
    const float* bo  = (const float*)d_in[8];
    const float* g1  = (const float*)d_in[9];
    const float* b1  = (const float*)d_in[10];
    const float* W1  = (const float*)d_in[11];
    const float* bf1 = (const float*)d_in[12];
    const float* W2  = (const float*)d_in[13];
    const float* bf2 = (const float*)d_in[14];
    const float* g2  = (const float*)d_in[15];
    const float* b2  = (const float*)d_in[16];
    float* out = (float*)d_out;

    __nv_bfloat16 *xh,*xl,*Wqvh,*Wqvl,*Woh,*Wol,*W1h,*W1l,*W2h,*W2l;
    __nv_bfloat16 *Qbh,*Qbl,*Vbh,*Vbl,*ctxh,*ctxl,*ph,*pl,*h1h,*h1l;
    float *attp,*postp,*ffp;
    cudaGetSymbolAddress((void**)&xh,  g_xh);  cudaGetSymbolAddress((void**)&xl,  g_xl);
    cudaGetSymbolAddress((void**)&Wqvh,g_Wqvh);cudaGetSymbolAddress((void**)&Wqvl,g_Wqvl);
    cudaGetSymbolAddress((void**)&Woh, g_Woh); cudaGetSymbolAddress((void**)&Wol, g_Wol);
    cudaGetSymbolAddress((void**)&W1h, g_W1h); cudaGetSymbolAddress((void**)&W1l, g_W1l);
    cudaGetSymbolAddress((void**)&W2h, g_W2h); cudaGetSymbolAddress((void**)&W2l, g_W2l);
    cudaGetSymbolAddress((void**)&Qbh, g_Qh);  cudaGetSymbolAddress((void**)&Qbl, g_Ql);
    cudaGetSymbolAddress((void**)&Vbh, g_Vh);  cudaGetSymbolAddress((void**)&Vbl, g_Vl);
    cudaGetSymbolAddress((void**)&ctxh,g_ctxh);cudaGetSymbolAddress((void**)&ctxl,g_ctxl);
    cudaGetSymbolAddress((void**)&attp,g_att); cudaGetSymbolAddress((void**)&postp,g_post);
    cudaGetSymbolAddress((void**)&ph,  g_ph);  cudaGetSymbolAddress((void**)&pl,  g_pl);
    cudaGetSymbolAddress((void**)&h1h, g_h1h); cudaGetSymbolAddress((void**)&h1l, g_h1l);
    cudaGetSymbolAddress((void**)&ffp, g_ff);

    cudaFuncSetAttribute(mma_gemm<EPI_PLAIN>,   cudaFuncAttributeMaxDynamicSharedMemorySize, GSMEM);
    cudaFuncSetAttribute(mma_gemm<EPI_RELU_HL>, cudaFuncAttributeMaxDynamicSharedMemorySize, GSMEM);
    cudaFuncSetAttribute(mma_gemm<EPI_QV>,      cudaFuncAttributeMaxDynamicSharedMemorySize, GSMEM);
    cudaFuncSetAttribute(attn_mma, cudaFuncAttributeMaxDynamicSharedMemorySize, ATT_SMEM);

    dim3 blk(256);
    dim3 tblk(32, 8);

    // input / weight conversion (hi/lo split; weights transposed to [N][K])
    convert_hl<<<NTOK*EMB/4/256, blk>>>((const float4*)x, xh, xl, NTOK*EMB/4);
    conv_transpose<<<dim3(EMB/32, EMB/32), tblk>>>(Wq, Wqvh, Wqvl, EMB, EMB);
    conv_transpose<<<dim3(EMB/32, EMB/32), tblk>>>(Wv, Wqvh + (size_t)EMB*EMB,
                                                   Wqvl + (size_t)EMB*EMB, EMB, EMB);
    conv_transpose<<<dim3(EMB/32, EMB/32), tblk>>>(Wo, Woh, Wol, EMB, EMB);
    conv_transpose<<<dim3(FFN/32, EMB/32), tblk>>>(W1, W1h, W1l, EMB, FFN);
    conv_transpose<<<dim3(EMB/32, FFN/32), tblk>>>(W2, W2h, W2l, FFN, EMB);

    // fused Q+V projection -> [b,h,l,d] bf16 hi/lo (Q pre-scaled by 1/8)
    mma_gemm<EPI_QV><<<dim3(2*EMB/256, NTOK/128), blk, GSMEM>>>(
        xh, xl, Wqvh, Wqvl, bq, bv, nullptr, Qbh, Qbl, Vbh, Vbl, NTOK, 2*EMB, EMB);

    // tensor-core flash attention -> ctx hi/lo [tok][E]
    attn_mma<<<dim3(SEQL/128, BATCH*HEADS), blk, ATT_SMEM>>>(Qbh, Qbl, Vbh, Vbl, ctxh, ctxl);

    // output projection -> att fp32
    mma_gemm<EPI_PLAIN><<<dim3(EMB/256, NTOK/128), blk, GSMEM>>>(
        ctxh, ctxl, Woh, Wol, bo, nullptr, attp, nullptr, nullptr, nullptr, nullptr,
        NTOK, EMB, EMB);

    // post = LN(x + att), plus hi/lo for FFN input
    add_ln_kernel<true><<<NTOK, blk>>>(x, attp, g1, b1, postp, ph, pl);

    // FFN
    mma_gemm<EPI_RELU_HL><<<dim3(FFN/256, NTOK/128), blk, GSMEM>>>(
        ph, pl, W1h, W1l, bf1, nullptr, nullptr, h1h, h1l, nullptr, nullptr,
        NTOK, FFN, EMB);
    mma_gemm<EPI_PLAIN><<<dim3(EMB/256, NTOK/128), blk, GSMEM>>>(
        h1h, h1l, W2h, W2l, bf2, nullptr, ffp, nullptr, nullptr, nullptr, nullptr,
        NTOK, EMB, FFN);

    // out = LN(post + ff)
    add_ln_kernel<false><<<NTOK, blk>>>(postp, ffp, g2, b2, out, nullptr, nullptr);
}

// round 15
// speedup vs baseline: 1.0037x; 1.0013x over previous
#include <cuda_runtime.h>
#include <cuda_bf16.h>
#include <math.h>
#include <float.h>
#include <stdint.h>

// Problem constants
#define BATCH 2
#define SEQL  2048
#define EMB   1024
#define HEADS 16
#define DHEAD 64
#define FFN   4096
#define NTOK  (BATCH*SEQL)   // 4096
#define LN_EPS 1e-5f

// ================= scratch (device globals; no allocation allowed) ==========
__device__ __align__(16) __nv_bfloat16 g_xh [NTOK*EMB], g_xl [NTOK*EMB];
__device__ __align__(16) __nv_bfloat16 g_Wqvh[2*EMB*EMB], g_Wqvl[2*EMB*EMB]; // [N=2048][K=1024]
__device__ __align__(16) __nv_bfloat16 g_Woh[EMB*EMB],  g_Wol[EMB*EMB];
__device__ __align__(16) __nv_bfloat16 g_W1h[EMB*FFN],  g_W1l[EMB*FFN];   // [N=FFN][K=EMB]
__device__ __align__(16) __nv_bfloat16 g_W2h[EMB*FFN],  g_W2l[EMB*FFN];   // [N=EMB][K=FFN]
__device__ __align__(16) __nv_bfloat16 g_Qh [NTOK*EMB], g_Ql [NTOK*EMB];  // [b,h,l,d], pre-scaled 1/8
__device__ __align__(16) __nv_bfloat16 g_Vh [NTOK*EMB], g_Vl [NTOK*EMB];  // [b,h,l,d]
__device__ __align__(16) __nv_bfloat16 g_ctxh[NTOK*EMB], g_ctxl[NTOK*EMB];
__device__ float g_att [NTOK*EMB];
__device__ float g_post[NTOK*EMB];
__device__ __align__(16) __nv_bfloat16 g_ph[NTOK*EMB],  g_pl[NTOK*EMB];
__device__ __align__(16) __nv_bfloat16 g_h1h[NTOK*FFN], g_h1l[NTOK*FFN];
__device__ float g_ff  [NTOK*EMB];

// ================= helpers ==================================================
__device__ __forceinline__ uint32_t smem_u32(const void* p) {
    uint32_t a;
    asm("{ .reg .u64 t; cvta.to.shared.u64 t, %1; cvt.u32.u64 %0, t; }" : "=r"(a) : "l"(p));
    return a;
}
__device__ __forceinline__ void cpa16(uint32_t s, const void* g) {
    asm volatile("cp.async.cg.shared.global [%0], [%1], 16;" :: "r"(s), "l"(g) : "memory");
}
#define CP_COMMIT() asm volatile("cp.async.commit_group;" ::: "memory")

#define LDSM4(r, addr) \
    asm volatile("ldmatrix.sync.aligned.m8n8.x4.shared.b16 {%0,%1,%2,%3}, [%4];" \
        : "=r"((r)[0]), "=r"((r)[1]), "=r"((r)[2]), "=r"((r)[3]) : "r"(addr))

#define MMA16816(c, a, b0, b1) \
    asm volatile("mma.sync.aligned.m16n8k16.row.col.f32.bf16.bf16.f32 " \
        "{%0,%1,%2,%3}, {%4,%5,%6,%7}, {%8,%9}, {%0,%1,%2,%3};" \
        : "+f"((c)[0]), "+f"((c)[1]), "+f"((c)[2]), "+f"((c)[3]) \
        : "r"((a)[0]), "r"((a)[1]), "r"((a)[2]), "r"((a)[3]), "r"(b0), "r"(b1))

__device__ __forceinline__ void split2(float v0, float v1, uint32_t& hi, uint32_t& lo) {
    __nv_bfloat162 hp, lp;
    hp.x = __float2bfloat16(v0); hp.y = __float2bfloat16(v1);
    lp.x = __float2bfloat16(v0 - __bfloat162float(hp.x));
    lp.y = __float2bfloat16(v1 - __bfloat162float(hp.y));
    hi = *(uint32_t*)&hp; lo = *(uint32_t*)&lp;
}

// ================= mma.sync split-bf16 GEMM =================================
// C[M,N] = A[M,K] @ Bt[N,K]^T (+bias, epilogue). A,B given as (hi,lo) bf16 pairs.
// CTA tile 128x256, 8 warps (2x4) x warp tile 64x64, K-chunk 64, 2-stage pipe.
#define EPI_PLAIN    0
#define EPI_RELU_HL  1
#define EPI_QV       2

#define ROWB  144
#define MAT_A (128*ROWB)              // 18432
#define MAT_B (256*ROWB)              // 36864
#define STAGE (2*MAT_A + 2*MAT_B)     // 110592
#define GSMEM (2*STAGE)               // 221184

__device__ __forceinline__ void g_load_chunk(uint32_t stg,
        const char* ah, const char* al, const char* bh, const char* bl,
        size_t rowb, size_t ko, int t)
{
#pragma unroll
    for (int i = t; i < 2048; i += 256) {          // A: 2 mats x 128 rows x 8x16B
        int mat = i >> 10, idx = i & 1023, row = idx >> 3, c = idx & 7;
        cpa16(stg + mat*MAT_A + row*ROWB + c*16,
              (mat ? al : ah) + (size_t)row*rowb + ko + c*16);
    }
#pragma unroll
    for (int i = t; i < 4096; i += 256) {          // B: 2 mats x 256 rows x 8x16B
        int mat = i >> 11, idx = i & 2047, row = idx >> 3, c = idx & 7;
        cpa16(stg + 2*MAT_A + mat*MAT_B + row*ROWB + c*16,
              (mat ? bl : bh) + (size_t)row*rowb + ko + c*16);
    }
    CP_COMMIT();
}

template<int EPI>
__global__ __launch_bounds__(256, 1)
void mma_gemm(const __nv_bfloat16* __restrict__ Ah, const __nv_bfloat16* __restrict__ Al,
              const __nv_bfloat16* __restrict__ Bh, const __nv_bfloat16* __restrict__ Bl,
              const float* __restrict__ bias, const float* __restrict__ bias2,
              float* __restrict__ Cf, __nv_bfloat16* __restrict__ Ch, __nv_bfloat16* __restrict__ Cl,
              __nv_bfloat16* __restrict__ C2h, __nv_bfloat16* __restrict__ C2l,
              int M, int N, int K)
{
    extern __shared__ char smem[];
    const uint32_t sb = smem_u32(smem);
    const int t = threadIdx.x, wid = t >> 5, lane = t & 31;
    const int bm = blockIdx.y, bn = blockIdx.x;
    const int wm = wid >> 2, wn = wid & 3;

    const size_t rowb = (size_t)K * 2;
    const char* Abh = (const char*)Ah + (size_t)bm*128*rowb;
    const char* Abl = (const char*)Al + (size_t)bm*128*rowb;
    const char* Bbh = (const char*)Bh + (size_t)bn*256*rowb;
    const char* Bbl = (const char*)Bl + (size_t)bn*256*rowb;

    float acc[4][8][4];
#pragma unroll
    for (int i = 0; i < 4; i++)
#pragma unroll
        for (int j = 0; j < 8; j++)
#pragma unroll
            for (int r = 0; r < 4; r++) acc[i][j][r] = 0.f;

    const int nch = K >> 6;
    g_load_chunk(sb,         Abh, Abl, Bbh, Bbl, rowb, 0,   t);
    g_load_chunk(sb + STAGE, Abh, Abl, Bbh, Bbl, rowb, 128, t);

    const int lr = lane & 15;
    const int lc = (lane >> 4) * 16;

    for (int kc = 0; kc < nch; kc++) {
        const int s = kc & 1;
        const uint32_t stg = sb + s*STAGE;
        if (kc + 1 < nch) asm volatile("cp.async.wait_group 1;" ::: "memory");
        else              asm volatile("cp.async.wait_group 0;" ::: "memory");
        __syncthreads();

        const uint32_t a_h = stg,              a_l = stg + MAT_A;
        const uint32_t b_h = stg + 2*MAT_A,    b_l = stg + 2*MAT_A + MAT_B;

#pragma unroll
        for (int ks = 0; ks < 4; ks++) {
            const uint32_t koff = ks*32 + lc;
            uint32_t ah[4][4], al[4][4];
#pragma unroll
            for (int mt = 0; mt < 4; mt++) {
                const uint32_t ro = (wm*64 + mt*16 + lr)*ROWB + koff;
                LDSM4(ah[mt], a_h + ro);
                LDSM4(al[mt], a_l + ro);
            }
#pragma unroll
            for (int h2 = 0; h2 < 4; h2++) {
                uint32_t bhf[4], blf[4];
                const uint32_t ro = (wn*64 + h2*16 + lr)*ROWB + koff;
                LDSM4(bhf, b_h + ro);
                LDSM4(blf, b_l + ro);
#pragma unroll
                for (int q = 0; q < 2; q++) {
                    const int nt = h2*2 + q;
#pragma unroll
                    for (int mt = 0; mt < 4; mt++) {
                        MMA16816(acc[mt][nt], ah[mt], bhf[q], bhf[2+q]); // hi*hi
                        MMA16816(acc[mt][nt], ah[mt], blf[q], blf[2+q]); // hi*lo
                        MMA16816(acc[mt][nt], al[mt], bhf[q], bhf[2+q]); // lo*hi
                    }
                }
            }
        }
        __syncthreads();
        if (kc + 2 < nch)
            g_load_chunk(stg, Abh, Abl, Bbh, Bbl, rowb, (size_t)(kc + 2)*128, t);
    }

    // ---- epilogue straight from registers
    const int qr = lane >> 2, qc = (lane & 3) * 2;
#pragma unroll
    for (int nt = 0; nt < 8; nt++) {
        const int gc = bn*256 + wn*64 + nt*8 + qc;
#pragma unroll
        for (int mt = 0; mt < 4; mt++) {
            const int gr = bm*128 + wm*64 + mt*16 + qr;
#pragma unroll
            for (int half = 0; half < 2; half++) {
                const int row = gr + half*8;
                if (EPI == EPI_PLAIN) {
                    const float v0 = acc[mt][nt][2*half+0] + bias[gc];
                    const float v1 = acc[mt][nt][2*half+1] + bias[gc+1];
                    *(float2*)(Cf + (size_t)row*N + gc) = make_float2(v0, v1);
                } else if (EPI == EPI_RELU_HL) {
                    const float v0 = fmaxf(acc[mt][nt][2*half+0] + bias[gc],   0.f);
                    const float v1 = fmaxf(acc[mt][nt][2*half+1] + bias[gc+1], 0.f);
                    uint32_t hp, lp;
                    split2(v0, v1, hp, lp);
                    *(uint32_t*)(Ch + (size_t)row*N + gc) = hp;
                    *(uint32_t*)(Cl + (size_t)row*N + gc) = lp;
                } else { // EPI_QV: cols [0,1024) -> Q (scaled 1/8), [1024,2048) -> V
                    const int isv = gc >> 10, hcol = gc & 1023;
                    const float* bp = isv ? bias2 : bias;
                    const float sc = isv ? 1.f : 0.125f;
                    const float v0 = (acc[mt][nt][2*half+0] + bp[hcol])   * sc;
                    const float v1 = (acc[mt][nt][2*half+1] + bp[hcol+1]) * sc;
                    const int h = hcol >> 6, d = hcol & 63;
                    const int b = row >> 11, ltok = row & 2047;
                    const size_t off = ((size_t)(b*HEADS + h)*SEQL + ltok)*DHEAD + d;
                    uint32_t hp, lp;
                    split2(v0, v1, hp, lp);
                    *(uint32_t*)((isv ? C2h : Ch) + off) = hp;
                    *(uint32_t*)((isv ? C2l : Cl) + off) = lp;
                }
            }
        }
    }
}

// ================= conversion kernels =======================================
__global__ __launch_bounds__(256)
void convert_hl(const float4* __restrict__ in, __nv_bfloat16* __restrict__ h,
                __nv_bfloat16* __restrict__ l, int n4)
{
    int i = blockIdx.x*256 + threadIdx.x;
    if (i >= n4) return;
    float4 v = in[i];
    uint32_t h0, l0, h1, l1;
    split2(v.x, v.y, h0, l0);
    split2(v.z, v.w, h1, l1);
    ((uint32_t*)h)[2*i]   = h0; ((uint32_t*)h)[2*i+1] = h1;
    ((uint32_t*)l)[2*i]   = l0; ((uint32_t*)l)[2*i+1] = l1;
}

// W[K][N] fp32 -> Th/Tl[N][K] bf16 (transposed split)
__global__ void conv_transpose(const float* __restrict__ W, __nv_bfloat16* __restrict__ Th,
                               __nv_bfloat16* __restrict__ Tl, int K, int N)
{
    __shared__ float tile[32][33];
    const int n0 = blockIdx.x*32, k0 = blockIdx.y*32;
    const int tx = threadIdx.x, ty = threadIdx.y;
#pragma unroll
    for (int i = ty; i < 32; i += 8)
        tile[i][tx] = W[(size_t)(k0+i)*N + n0 + tx];
    __syncthreads();
#pragma unroll
    for (int i = ty; i < 32; i += 8) {
        float v = tile[tx][i];
        __nv_bfloat16 h = __float2bfloat16(v);
        Th[(size_t)(n0+i)*K + k0 + tx] = h;
        Tl[(size_t)(n0+i)*K + k0 + tx] = __float2bfloat16(v - __bfloat162float(h));
    }
}

// ================= tensor-core flash attention ==============================
#define AROW 144
#define SQ_L (128*AROW)
#define SSTG (2*128*AROW)
#define STG_SZ (4*64*AROW)
#define ATT_SMEM (SSTG + 2*STG_SZ)    // 110592

__global__ __launch_bounds__(256)
void attn_mma(const __nv_bfloat16* __restrict__ Qh, const __nv_bfloat16* __restrict__ Ql,
              const __nv_bfloat16* __restrict__ Vh, const __nv_bfloat16* __restrict__ Vl,
              __nv_bfloat16* __restrict__ ctxh, __nv_bfloat16* __restrict__ ctxl)
{
    extern __shared__ char smem[];
    const uint32_t sb = smem_u32(smem);
    const int t = threadIdx.x, wid = t >> 5, lane = t & 31;
    const int qt = blockIdx.x, bh = blockIdx.y;

    const char* Qbh = (const char*)(Qh + ((size_t)bh*SEQL + qt*128)*DHEAD);
    const char* Qbl = (const char*)(Ql + ((size_t)bh*SEQL + qt*128)*DHEAD);
    const char* Vbh = (const char*)(Vh + (size_t)bh*SEQL*DHEAD);
    const char* Vbl = (const char*)(Vl + (size_t)bh*SEQL*DHEAD);

#pragma unroll
    for (int i = t; i < 1024; i += 256) {
        int r = i >> 3, c = i & 7;
        cpa16(sb + r*AROW + c*16,        Qbh + r*128 + c*16);
        cpa16(sb + SQ_L + r*AROW + c*16, Qbl + r*128 + c*16);
    }
#pragma unroll
    for (int i = t; i < 512; i += 256) {
        int r = i >> 3, c = i & 7;
        cpa16(sb + SSTG + r*AROW + c*16,           Vbh + r*128 + c*16);
        cpa16(sb + SSTG + 64*AROW + r*AROW + c*16, Vbl + r*128 + c*16);
    }
    CP_COMMIT();

    const int lr = lane & 15;
    const int lc = (lane >> 4) * 16;

    uint32_t qfh[4][4], qfl[4][4];
    float m[2] = {-FLT_MAX, -FLT_MAX}, lsum[2] = {0.f, 0.f};
    float o[8][4];
#pragma unroll
    for (int nt = 0; nt < 8; nt++)
#pragma unroll
        for (int r = 0; r < 4; r++) o[nt][r] = 0.f;

    for (int kt = 0; kt < SEQL/64; kt++) {
        const int s = kt & 1;
        const uint32_t stg = sb + SSTG + s*STG_SZ;

        if (kt + 1 < SEQL/64) {
            const uint32_t nstg = sb + SSTG + (1-s)*STG_SZ;
            const char* nh = Vbh + (size_t)(kt+1)*64*128;
            const char* nl = Vbl + (size_t)(kt+1)*64*128;
#pragma unroll
            for (int i = t; i < 512; i += 256) {
                int r = i >> 3, c = i & 7;
                cpa16(nstg + r*AROW + c*16,           nh + r*128 + c*16);
                cpa16(nstg + 64*AROW + r*AROW + c*16, nl + r*128 + c*16);
            }
            CP_COMMIT();
            asm volatile("cp.async.wait_group 1;" ::: "memory");
        } else {
            asm volatile("cp.async.wait_group 0;" ::: "memory");
        }
        __syncthreads();

        // transpose V tile: VS[k][d] -> VT[d][k] (hi & lo)
        {
            const uint32_t vsh = stg, vsl = stg + 64*AROW;
            const uint32_t vth = stg + 2*64*AROW, vtl = stg + 3*64*AROW;
#pragma unroll
            for (int i = t; i < 4096; i += 256) {
                int k = i >> 6, d = i & 63;
                uint16_t a, b2;
                asm volatile("ld.shared.u16 %0, [%1];" : "=h"(a)  : "r"(vsh + k*AROW + d*2));
                asm volatile("ld.shared.u16 %0, [%1];" : "=h"(b2) : "r"(vsl + k*AROW + d*2));
                asm volatile("st.shared.u16 [%0], %1;" :: "r"(vth + d*AROW + k*2), "h"(a));
                asm volatile("st.shared.u16 [%0], %1;" :: "r"(vtl + d*AROW + k*2), "h"(b2));
            }
        }
        __syncthreads();

        if (kt == 0) {
#pragma unroll
            for (int ks = 0; ks < 4; ks++) {
                const uint32_t ro = (wid*16 + lr)*AROW + ks*32 + lc;
                LDSM4(qfh[ks], sb + ro);
                LDSM4(qfl[ks], sb + SQ_L + ro);
            }
        }

        // ---- S = Q @ V^T
        float sc[8][4];
#pragma unroll
        for (int nt = 0; nt < 8; nt++)
#pragma unroll
            for (int r = 0; r < 4; r++) sc[nt][r] = 0.f;

#pragma unroll
        for (int ks = 0; ks < 4; ks++) {
            const uint32_t koff = ks*32 + lc;
#pragma unroll
            for (int h2 = 0; h2 < 4; h2++) {
                uint32_t bvh[4], bvl[4];
                const uint32_t ro = (h2*16 + lr)*AROW + koff;
                LDSM4(bvh, stg + ro);
                LDSM4(bvl, stg + 64*AROW + ro);
#pragma unroll
                for (int q = 0; q < 2; q++) {
                    const int nt = h2*2 + q;
                    MMA16816(sc[nt], qfh[ks], bvh[q], bvh[2+q]);
                    MMA16816(sc[nt], qfh[ks], bvl[q], bvl[2+q]);
                    MMA16816(sc[nt], qfl[ks], bvh[q], bvh[2+q]);
                }
            }
        }

        // ---- online softmax
#pragma unroll
        for (int i = 0; i < 2; i++) {
            float mx = -FLT_MAX;
#pragma unroll
            for (int nt = 0; nt < 8; nt++)
                mx = fmaxf(mx, fmaxf(sc[nt][2*i], sc[nt][2*i+1]));
            mx = fmaxf(mx, __shfl_xor_sync(0xffffffffu, mx, 1));
            mx = fmaxf(mx, __shfl_xor_sync(0xffffffffu, mx, 2));
            const float mnew = fmaxf(m[i], mx);
            const float alpha = __expf(m[i] - mnew);
            float rs = 0.f;
#pragma unroll
            for (int nt = 0; nt < 8; nt++) {
                sc[nt][2*i]   = __expf(sc[nt][2*i]   - mnew);
                sc[nt][2*i+1] = __expf(sc[nt][2*i+1] - mnew);
                rs += sc[nt][2*i] + sc[nt][2*i+1];
            }
            rs += __shfl_xor_sync(0xffffffffu, rs, 1);
            rs += __shfl_xor_sync(0xffffffffu, rs, 2);
            lsum[i] = lsum[i]*alpha + rs;
            m[i] = mnew;
#pragma unroll
            for (int nt = 0; nt < 8; nt++) {
                o[nt][2*i]   *= alpha;
                o[nt][2*i+1] *= alpha;
            }
        }

        // ---- pack P into A-fragments (hi/lo)
        uint32_t aph[4][4], apl[4][4];
#pragma unroll
        for (int k2 = 0; k2 < 4; k2++) {
            split2(sc[2*k2][0],   sc[2*k2][1],   aph[k2][0], apl[k2][0]);
            split2(sc[2*k2][2],   sc[2*k2][3],   aph[k2][1], apl[k2][1]);
            split2(sc[2*k2+1][0], sc[2*k2+1][1], aph[k2][2], apl[k2][2]);
            split2(sc[2*k2+1][2], sc[2*k2+1][3], aph[k2][3], apl[k2][3]);
        }

        // ---- O += P @ V
        const uint32_t vth = stg + 2*64*AROW, vtl = stg + 3*64*AROW;
#pragma unroll
        for (int k2 = 0; k2 < 4; k2++) {
            const uint32_t koff = k2*32 + lc;
#pragma unroll
            for (int h2 = 0; h2 < 4; h2++) {
                uint32_t bth[4], btl[4];
                const uint32_t ro = (h2*16 + lr)*AROW + koff;
                LDSM4(bth, vth + ro);
                LDSM4(btl, vtl + ro);
#pragma unroll
                for (int q = 0; q < 2; q++) {
                    const int nt = h2*2 + q;
                    MMA16816(o[nt], aph[k2], bth[q], bth[2+q]);
                    MMA16816(o[nt], apl[k2], bth[q], bth[2+q]);
                    MMA16816(o[nt], aph[k2], btl[q], btl[2+q]);
                }
            }
        }
        __syncthreads();
    }

    // ---- epilogue
    const int g = lane >> 2, qc = (lane & 3)*2;
    const int b = bh >> 4, h = bh & 15;
#pragma unroll
    for (int i = 0; i < 2; i++) {
        const float inv = 1.f / lsum[i];
        const int ltok = qt*128 + wid*16 + g + i*8;
        const size_t rowoff = (size_t)(b*SEQL + ltok)*EMB + h*DHEAD;
#pragma unroll
        for (int nt = 0; nt < 8; nt++) {
            uint32_t hp, lp;
            split2(o[nt][2*i]*inv, o[nt][2*i+1]*inv, hp, lp);
            *(uint32_t*)(ctxh + rowoff + nt*8 + qc) = hp;
            *(uint32_t*)(ctxl + rowoff + nt*8 + qc) = lp;
        }
    }
}

// ================= fused residual add + LayerNorm ===========================
template<bool HL>
__global__ __launch_bounds__(256)
void add_ln_kernel(const float* __restrict__ a, const float* __restrict__ bres,
                   const float* __restrict__ gamma, const float* __restrict__ beta,
                   float* __restrict__ out,
                   __nv_bfloat16* __restrict__ oh, __nv_bfloat16* __restrict__ ol)
{
    const int row = blockIdx.x;
    const int t = threadIdx.x;
    const int lane = t & 31, wid = t >> 5;

    const float4* ap = (const float4*)(a + (size_t)row * EMB);
    const float4* bp = (const float4*)(bres + (size_t)row * EMB);
    float4 av = ap[t], bv = bp[t];
    float v0 = av.x + bv.x, v1 = av.y + bv.y, v2 = av.z + bv.z, v3 = av.w + bv.w;

    float sum = v0 + v1 + v2 + v3;
    float sq  = v0*v0 + v1*v1 + v2*v2 + v3*v3;
#pragma unroll
    for (int off = 16; off >= 1; off >>= 1) {
        sum += __shfl_xor_sync(0xffffffffu, sum, off);
        sq  += __shfl_xor_sync(0xffffffffu, sq, off);
    }
    __shared__ float ssum[8], ssq[8], s_mean, s_rstd;
    if (lane == 0) { ssum[wid] = sum; ssq[wid] = sq; }
    __syncthreads();
    if (t == 0) {
        float S = 0.f, Q = 0.f;
#pragma unroll
        for (int w = 0; w < 8; w++) { S += ssum[w]; Q += ssq[w]; }
        float mean = S * (1.f/EMB);
        float var  = Q * (1.f/EMB) - mean*mean;
        s_mean = mean;
        s_rstd = rsqrtf(var + LN_EPS);
    }
    __syncthreads();
    const float mean = s_mean, rstd = s_rstd;

    float4 g = ((const float4*)gamma)[t], bt = ((const float4*)beta)[t];
    float4 r;
    r.x = (v0 - mean) * rstd * g.x + bt.x;
    r.y = (v1 - mean) * rstd * g.y + bt.y;
    r.z = (v2 - mean) * rstd * g.z + bt.z;
    r.w = (v3 - mean) * rstd * g.w + bt.w;
    ((float4*)(out + (size_t)row * EMB))[t] = r;

    if (HL) {
        size_t off = (size_t)row * EMB + 4*t;
        uint32_t h0, l0, h1, l1;
        split2(r.x, r.y, h0, l0);
        split2(r.z, r.w, h1, l1);
        *(uint32_t*)(oh + off)     = h0;
        *(uint32_t*)(oh + off + 2) = h1;
        *(uint32_t*)(ol + off)     = l0;
        *(uint32_t*)(ol + off + 2) = l1;
    }
}

// ================= launch ====================================================
extern "C" void kernel_launch(void* const* d_in, const int* in_sizes, int n_in,
                              void* d_out, int out_size)
{
    const float* x   = (const float*)d_in[0];
    const float* Wq  = (const float*)d_in[1];
    const float* bq  = (const float*)d_in[2];
    // d_in[3], d_in[4] = Wk, bk: dead code in the reference (scores use Q@V^T)
    const float* Wv  = (const float*)d_in[5];
    const float* bv  = (const float*)d_in[6];
    const float* Wo  = (const float*)d_in[7];
    const float* bo  = (const float*)d_in[8];
    const float* g1  = (const float*)d_in[9];
    const float* b1  = (const float*)d_in[10];
    const float* W1  = (const float*)d_in[11];
    const float* bf1 = (const float*)d_in[12];
    const float* W2  = (const float*)d_in[13];
    const float* bf2 = (const float*)d_in[14];
    const float* g2  = (const float*)d_in[15];
    const float* b2  = (const float*)d_in[16];
    float* out = (float*)d_out;

    __nv_bfloat16 *xh,*xl,*Wqvh,*Wqvl,*Woh,*Wol,*W1h,*W1l,*W2h,*W2l;
    __nv_bfloat16 *Qbh,*Qbl,*Vbh,*Vbl,*ctxh,*ctxl,*ph,*pl,*h1h,*h1l;
    float *attp,*postp,*ffp;
    cudaGetSymbolAddress((void**)&xh,  g_xh);  cudaGetSymbolAddress((void**)&xl,  g_xl);
    cudaGetSymbolAddress((void**)&Wqvh,g_Wqvh);cudaGetSymbolAddress((void**)&Wqvl,g_Wqvl);
    cudaGetSymbolAddress((void**)&Woh, g_Woh); cudaGetSymbolAddress((void**)&Wol, g_Wol);
    cudaGetSymbolAddress((void**)&W1h, g_W1h); cudaGetSymbolAddress((void**)&W1l, g_W1l);
    cudaGetSymbolAddress((void**)&W2h, g_W2h); cudaGetSymbolAddress((void**)&W2l, g_W2l);
    cudaGetSymbolAddress((void**)&Qbh, g_Qh);  cudaGetSymbolAddress((void**)&Qbl, g_Ql);
    cudaGetSymbolAddress((void**)&Vbh, g_Vh);  cudaGetSymbolAddress((void**)&Vbl, g_Vl);
    cudaGetSymbolAddress((void**)&ctxh,g_ctxh);cudaGetSymbolAddress((void**)&ctxl,g_ctxl);
    cudaGetSymbolAddress((void**)&attp,g_att); cudaGetSymbolAddress((void**)&postp,g_post);
    cudaGetSymbolAddress((void**)&ph,  g_ph);  cudaGetSymbolAddress((void**)&pl,  g_pl);
    cudaGetSymbolAddress((void**)&h1h, g_h1h); cudaGetSymbolAddress((void**)&h1l, g_h1l);
    cudaGetSymbolAddress((void**)&ffp, g_ff);

    cudaFuncSetAttribute(mma_gemm<EPI_PLAIN>,   cudaFuncAttributeMaxDynamicSharedMemorySize, GSMEM);
    cudaFuncSetAttribute(mma_gemm<EPI_RELU_HL>, cudaFuncAttributeMaxDynamicSharedMemorySize, GSMEM);
    cudaFuncSetAttribute(mma_gemm<EPI_QV>,      cudaFuncAttributeMaxDynamicSharedMemorySize, GSMEM);
    cudaFuncSetAttribute(attn_mma, cudaFuncAttributeMaxDynamicSharedMemorySize, ATT_SMEM);

    dim3 blk(256);
    dim3 tblk(32, 8);

    // input / weight conversion (hi/lo split; weights transposed to [N][K])
    convert_hl<<<NTOK*EMB/4/256, blk>>>((const float4*)x, xh, xl, NTOK*EMB/4);
    conv_transpose<<<dim3(EMB/32, EMB/32), tblk>>>(Wq, Wqvh, Wqvl, EMB, EMB);
    conv_transpose<<<dim3(EMB/32, EMB/32), tblk>>>(Wv, Wqvh + (size_t)EMB*EMB,
                                                   Wqvl + (size_t)EMB*EMB, EMB, EMB);
    conv_transpose<<<dim3(EMB/32, EMB/32), tblk>>>(Wo, Woh, Wol, EMB, EMB);
    conv_transpose<<<dim3(FFN/32, EMB/32), tblk>>>(W1, W1h, W1l, EMB, FFN);
    conv_transpose<<<dim3(EMB/32, FFN/32), tblk>>>(W2, W2h, W2l, FFN, EMB);

    // fused Q+V projection -> [b,h,l,d] bf16 hi/lo (Q pre-scaled by 1/8)
    mma_gemm<EPI_QV><<<dim3(2*EMB/256, NTOK/128), blk, GSMEM>>>(
        xh, xl, Wqvh, Wqvl, bq, bv, nullptr, Qbh, Qbl, Vbh, Vbl, NTOK, 2*EMB, EMB);

    // tensor-core flash attention -> ctx hi/lo [tok][E]
    attn_mma<<<dim3(SEQL/128, BATCH*HEADS), blk, ATT_SMEM>>>(Qbh, Qbl, Vbh, Vbl, ctxh, ctxl);

    // output projection -> att fp32
    mma_gemm<EPI_PLAIN><<<dim3(EMB/256, NTOK/128), blk, GSMEM>>>(
        ctxh, ctxl, Woh, Wol, bo, nullptr, attp, nullptr, nullptr, nullptr, nullptr,
        NTOK, EMB, EMB);

    // post = LN(x + att), plus hi/lo for FFN input
    add_ln_kernel<true><<<NTOK, blk>>>(x, attp, g1, b1, postp, ph, pl);

    // FFN
    mma_gemm<EPI_RELU_HL><<<dim3(FFN/256, NTOK/128), blk, GSMEM>>>(
        ph, pl, W1h, W1l, bf1, nullptr, nullptr, h1h, h1l, nullptr, nullptr,
        NTOK, FFN, EMB);
    mma_gemm<EPI_PLAIN><<<dim3(EMB/256, NTOK/128), blk, GSMEM>>>(
        h1h, h1l, W2h, W2l, bf2, nullptr, ffp, nullptr, nullptr, nullptr, nullptr,
        NTOK, EMB, FFN);

    // out = LN(post + ff)
    add_ln_kernel<false><<<NTOK, blk>>>(postp, ffp, g2, b2, out, nullptr, nullptr);
}

// round 16
// speedup vs baseline: 1.0065x; 1.0027x over previous
#include <cuda_runtime.h>
#include <cuda_bf16.h>
#include <math.h>
#include <float.h>
#include <stdint.h>

// Problem constants
#define BATCH 2
#define SEQL  2048
#define EMB   1024
#define HEADS 16
#define DHEAD 64
#define FFN   4096
#define NTOK  (BATCH*SEQL)   // 4096
#define LN_EPS 1e-5f

// ================= scratch (device globals; no allocation allowed) ==========
__device__ __align__(16) __nv_bfloat16 g_xh [NTOK*EMB], g_xl [NTOK*EMB];
__device__ __align__(16) __nv_bfloat16 g_Wqvh[2*EMB*EMB], g_Wqvl[2*EMB*EMB]; // [N=2048][K=1024]
__device__ __align__(16) __nv_bfloat16 g_Woh[EMB*EMB],  g_Wol[EMB*EMB];
__device__ __align__(16) __nv_bfloat16 g_W1h[EMB*FFN],  g_W1l[EMB*FFN];   // [N=FFN][K=EMB]
__device__ __align__(16) __nv_bfloat16 g_W2h[EMB*FFN],  g_W2l[EMB*FFN];   // [N=EMB][K=FFN]
__device__ __align__(16) __nv_bfloat16 g_Qh [NTOK*EMB], g_Ql [NTOK*EMB];  // [b,h,l,d], pre-scaled 1/8
__device__ __align__(16) __nv_bfloat16 g_Vh [NTOK*EMB], g_Vl [NTOK*EMB];  // [b,h,l,d]
__device__ __align__(16) __nv_bfloat16 g_ctxh[NTOK*EMB], g_ctxl[NTOK*EMB];
__device__ float g_att [NTOK*EMB];
__device__ float g_post[NTOK*EMB];
__device__ __align__(16) __nv_bfloat16 g_ph[NTOK*EMB],  g_pl[NTOK*EMB];
__device__ __align__(16) __nv_bfloat16 g_h1h[NTOK*FFN], g_h1l[NTOK*FFN];
__device__ float g_ff  [NTOK*EMB];

// ================= helpers ==================================================
__device__ __forceinline__ uint32_t smem_u32(const void* p) {
    uint32_t a;
    asm("{ .reg .u64 t; cvta.to.shared.u64 t, %1; cvt.u32.u64 %0, t; }" : "=r"(a) : "l"(p));
    return a;
}
__device__ __forceinline__ void cpa16(uint32_t s, const void* g) {
    asm volatile("cp.async.cg.shared.global [%0], [%1], 16;" :: "r"(s), "l"(g) : "memory");
}
#define CP_COMMIT() asm volatile("cp.async.commit_group;" ::: "memory")

#define LDSM4(r, addr) \
    asm volatile("ldmatrix.sync.aligned.m8n8.x4.shared.b16 {%0,%1,%2,%3}, [%4];" \
        : "=r"((r)[0]), "=r"((r)[1]), "=r"((r)[2]), "=r"((r)[3]) : "r"(addr))

#define MMA16816(c, a, b0, b1) \
    asm volatile("mma.sync.aligned.m16n8k16.row.col.f32.bf16.bf16.f32 " \
        "{%0,%1,%2,%3}, {%4,%5,%6,%7}, {%8,%9}, {%0,%1,%2,%3};" \
        : "+f"((c)[0]), "+f"((c)[1]), "+f"((c)[2]), "+f"((c)[3]) \
        : "r"((a)[0]), "r"((a)[1]), "r"((a)[2]), "r"((a)[3]), "r"(b0), "r"(b1))

__device__ __forceinline__ void split2(float v0, float v1, uint32_t& hi, uint32_t& lo) {
    __nv_bfloat162 hp, lp;
    hp.x = __float2bfloat16(v0); hp.y = __float2bfloat16(v1);
    lp.x = __float2bfloat16(v0 - __bfloat162float(hp.x));
    lp.y = __float2bfloat16(v1 - __bfloat162float(hp.y));
    hi = *(uint32_t*)&hp; lo = *(uint32_t*)&lp;
}

// ================= mma.sync split-bf16 GEMM =================================
// C[M,N] = A[M,K] @ Bt[N,K]^T (+bias, epilogue). A,B given as (hi,lo) bf16 pairs.
// CTA tile 128x256, 8 warps (2x4) x warp tile 64x64, K-chunk 64, 2-stage pipe.
#define EPI_PLAIN    0
#define EPI_RELU_HL  1
#define EPI_QV       2

#define ROWB  144
#define MAT_A (128*ROWB)              // 18432
#define MAT_B (256*ROWB)              // 36864
#define STAGE (2*MAT_A + 2*MAT_B)     // 110592
#define GSMEM (2*STAGE)               // 221184

__device__ __forceinline__ void g_load_chunk(uint32_t stg,
        const char* ah, const char* al, const char* bh, const char* bl,
        size_t rowb, size_t ko, int t)
{
#pragma unroll
    for (int i = t; i < 2048; i += 256) {          // A: 2 mats x 128 rows x 8x16B
        int mat = i >> 10, idx = i & 1023, row = idx >> 3, c = idx & 7;
        cpa16(stg + mat*MAT_A + row*ROWB + c*16,
              (mat ? al : ah) + (size_t)row*rowb + ko + c*16);
    }
#pragma unroll
    for (int i = t; i < 4096; i += 256) {          // B: 2 mats x 256 rows x 8x16B
        int mat = i >> 11, idx = i & 2047, row = idx >> 3, c = idx & 7;
        cpa16(stg + 2*MAT_A + mat*MAT_B + row*ROWB + c*16,
              (mat ? bl : bh) + (size_t)row*rowb + ko + c*16);
    }
    CP_COMMIT();
}

template<int EPI>
__global__ __launch_bounds__(256, 1)
void mma_gemm(const __nv_bfloat16* __restrict__ Ah, const __nv_bfloat16* __restrict__ Al,
              const __nv_bfloat16* __restrict__ Bh, const __nv_bfloat16* __restrict__ Bl,
              const float* __restrict__ bias, const float* __restrict__ bias2,
              float* __restrict__ Cf, __nv_bfloat16* __restrict__ Ch, __nv_bfloat16* __restrict__ Cl,
              __nv_bfloat16* __restrict__ C2h, __nv_bfloat16* __restrict__ C2l,
              int M, int N, int K)
{
    extern __shared__ char smem[];
    const uint32_t sb = smem_u32(smem);
    const int t = threadIdx.x, wid = t >> 5, lane = t & 31;
    const int bm = blockIdx.y, bn = blockIdx.x;
    const int wm = wid >> 2, wn = wid & 3;

    const size_t rowb = (size_t)K * 2;
    const char* Abh = (const char*)Ah + (size_t)bm*128*rowb;
    const char* Abl = (const char*)Al + (size_t)bm*128*rowb;
    const char* Bbh = (const char*)Bh + (size_t)bn*256*rowb;
    const char* Bbl = (const char*)Bl + (size_t)bn*256*rowb;

    float acc[4][8][4];
#pragma unroll
    for (int i = 0; i < 4; i++)
#pragma unroll
        for (int j = 0; j < 8; j++)
#pragma unroll
            for (int r = 0; r < 4; r++) acc[i][j][r] = 0.f;

    const int nch = K >> 6;
    g_load_chunk(sb,         Abh, Abl, Bbh, Bbl, rowb, 0,   t);
    g_load_chunk(sb + STAGE, Abh, Abl, Bbh, Bbl, rowb, 128, t);

    const int lr = lane & 15;
    const int lc = (lane >> 4) * 16;

    for (int kc = 0; kc < nch; kc++) {
        const int s = kc & 1;
        const uint32_t stg = sb + s*STAGE;
        if (kc + 1 < nch) asm volatile("cp.async.wait_group 1;" ::: "memory");
        else              asm volatile("cp.async.wait_group 0;" ::: "memory");
        __syncthreads();

        const uint32_t a_h = stg,              a_l = stg + MAT_A;
        const uint32_t b_h = stg + 2*MAT_A,    b_l = stg + 2*MAT_A + MAT_B;

#pragma unroll
        for (int ks = 0; ks < 4; ks++) {
            const uint32_t koff = ks*32 + lc;
            uint32_t ah[4][4], al[4][4];
#pragma unroll
            for (int mt = 0; mt < 4; mt++) {
                const uint32_t ro = (wm*64 + mt*16 + lr)*ROWB + koff;
                LDSM4(ah[mt], a_h + ro);
                LDSM4(al[mt], a_l + ro);
            }
#pragma unroll
            for (int h2 = 0; h2 < 4; h2++) {
                uint32_t bhf[4], blf[4];
                const uint32_t ro = (wn*64 + h2*16 + lr)*ROWB + koff;
                LDSM4(bhf, b_h + ro);
                LDSM4(blf, b_l + ro);
#pragma unroll
                for (int q = 0; q < 2; q++) {
                    const int nt = h2*2 + q;
#pragma unroll
                    for (int mt = 0; mt < 4; mt++) {
                        MMA16816(acc[mt][nt], ah[mt], bhf[q], bhf[2+q]); // hi*hi
                        MMA16816(acc[mt][nt], ah[mt], blf[q], blf[2+q]); // hi*lo
                        MMA16816(acc[mt][nt], al[mt], bhf[q], bhf[2+q]); // lo*hi
                    }
                }
            }
        }
        __syncthreads();
        if (kc + 2 < nch)
            g_load_chunk(stg, Abh, Abl, Bbh, Bbl, rowb, (size_t)(kc + 2)*128, t);
    }

    // ---- epilogue straight from registers
    const int qr = lane >> 2, qc = (lane & 3) * 2;
#pragma unroll
    for (int nt = 0; nt < 8; nt++) {
        const int gc = bn*256 + wn*64 + nt*8 + qc;
#pragma unroll
        for (int mt = 0; mt < 4; mt++) {
            const int gr = bm*128 + wm*64 + mt*16 + qr;
#pragma unroll
            for (int half = 0; half < 2; half++) {
                const int row = gr + half*8;
                if (EPI == EPI_PLAIN) {
                    const float v0 = acc[mt][nt][2*half+0] + bias[gc];
                    const float v1 = acc[mt][nt][2*half+1] + bias[gc+1];
                    *(float2*)(Cf + (size_t)row*N + gc) = make_float2(v0, v1);
                } else if (EPI == EPI_RELU_HL) {
                    const float v0 = fmaxf(acc[mt][nt][2*half+0] + bias[gc],   0.f);
                    const float v1 = fmaxf(acc[mt][nt][2*half+1] + bias[gc+1], 0.f);
                    uint32_t hp, lp;
                    split2(v0, v1, hp, lp);
                    *(uint32_t*)(Ch + (size_t)row*N + gc) = hp;
                    *(uint32_t*)(Cl + (size_t)row*N + gc) = lp;
                } else { // EPI_QV: cols [0,1024) -> Q (scaled 1/8), [1024,2048) -> V
                    const int isv = gc >> 10, hcol = gc & 1023;
                    const float* bp = isv ? bias2 : bias;
                    const float sc = isv ? 1.f : 0.125f;
                    const float v0 = (acc[mt][nt][2*half+0] + bp[hcol])   * sc;
                    const float v1 = (acc[mt][nt][2*half+1] + bp[hcol+1]) * sc;
                    const int h = hcol >> 6, d = hcol & 63;
                    const int b = row >> 11, ltok = row & 2047;
                    const size_t off = ((size_t)(b*HEADS + h)*SEQL + ltok)*DHEAD + d;
                    uint32_t hp, lp;
                    split2(v0, v1, hp, lp);
                    *(uint32_t*)((isv ? C2h : Ch) + off) = hp;
                    *(uint32_t*)((isv ? C2l : Cl) + off) = lp;
                }
            }
        }
    }
}

// ================= conversion kernels =======================================
__global__ __launch_bounds__(256)
void convert_hl(const float4* __restrict__ in, __nv_bfloat16* __restrict__ h,
                __nv_bfloat16* __restrict__ l, int n4)
{
    int i = blockIdx.x*256 + threadIdx.x;
    if (i >= n4) return;
    float4 v = in[i];
    uint32_t h0, l0, h1, l1;
    split2(v.x, v.y, h0, l0);
    split2(v.z, v.w, h1, l1);
    ((uint32_t*)h)[2*i]   = h0; ((uint32_t*)h)[2*i+1] = h1;
    ((uint32_t*)l)[2*i]   = l0; ((uint32_t*)l)[2*i+1] = l1;
}

// W[K][N] fp32 -> Th/Tl[N][K] bf16 (transposed split)
__global__ void conv_transpose(const float* __restrict__ W, __nv_bfloat16* __restrict__ Th,
                               __nv_bfloat16* __restrict__ Tl, int K, int N)
{
    __shared__ float tile[32][33];
    const int n0 = blockIdx.x*32, k0 = blockIdx.y*32;
    const int tx = threadIdx.x, ty = threadIdx.y;
#pragma unroll
    for (int i = ty; i < 32; i += 8)
        tile[i][tx] = W[(size_t)(k0+i)*N + n0 + tx];
    __syncthreads();
#pragma unroll
    for (int i = ty; i < 32; i += 8) {
        float v = tile[tx][i];
        __nv_bfloat16 h = __float2bfloat16(v);
        Th[(size_t)(n0+i)*K + k0 + tx] = h;
        Tl[(size_t)(n0+i)*K + k0 + tx] = __float2bfloat16(v - __bfloat162float(h));
    }
}

// ================= tensor-core flash attention ==============================
#define AROW 144
#define SQ_L (128*AROW)
#define SSTG (2*128*AROW)
#define STG_SZ (4*64*AROW)
#define ATT_SMEM (SSTG + 2*STG_SZ)    // 110592

__global__ __launch_bounds__(256)
void attn_mma(const __nv_bfloat16* __restrict__ Qh, const __nv_bfloat16* __restrict__ Ql,
              const __nv_bfloat16* __restrict__ Vh, const __nv_bfloat16* __restrict__ Vl,
              __nv_bfloat16* __restrict__ ctxh, __nv_bfloat16* __restrict__ ctxl)
{
    extern __shared__ char smem[];
    const uint32_t sb = smem_u32(smem);
    const int t = threadIdx.x, wid = t >> 5, lane = t & 31;
    const int qt = blockIdx.x, bh = blockIdx.y;

    const char* Qbh = (const char*)(Qh + ((size_t)bh*SEQL + qt*128)*DHEAD);
    const char* Qbl = (const char*)(Ql + ((size_t)bh*SEQL + qt*128)*DHEAD);
    const char* Vbh = (const char*)(Vh + (size_t)bh*SEQL*DHEAD);
    const char* Vbl = (const char*)(Vl + (size_t)bh*SEQL*DHEAD);

#pragma unroll
    for (int i = t; i < 1024; i += 256) {
        int r = i >> 3, c = i & 7;
        cpa16(sb + r*AROW + c*16,        Qbh + r*128 + c*16);
        cpa16(sb + SQ_L + r*AROW + c*16, Qbl + r*128 + c*16);
    }
#pragma unroll
    for (int i = t; i < 512; i += 256) {
        int r = i >> 3, c = i & 7;
        cpa16(sb + SSTG + r*AROW + c*16,           Vbh + r*128 + c*16);
        cpa16(sb + SSTG + 64*AROW + r*AROW + c*16, Vbl + r*128 + c*16);
    }
    CP_COMMIT();

    const int lr = lane & 15;
    const int lc = (lane >> 4) * 16;

    uint32_t qfh[4][4], qfl[4][4];
    float m[2] = {-FLT_MAX, -FLT_MAX}, lsum[2] = {0.f, 0.f};
    float o[8][4];
#pragma unroll
    for (int nt = 0; nt < 8; nt++)
#pragma unroll
        for (int r = 0; r < 4; r++) o[nt][r] = 0.f;

    for (int kt = 0; kt < SEQL/64; kt++) {
        const int s = kt & 1;
        const uint32_t stg = sb + SSTG + s*STG_SZ;

        if (kt + 1 < SEQL/64) {
            const uint32_t nstg = sb + SSTG + (1-s)*STG_SZ;
            const char* nh = Vbh + (size_t)(kt+1)*64*128;
            const char* nl = Vbl + (size_t)(kt+1)*64*128;
#pragma unroll
            for (int i = t; i < 512; i += 256) {
                int r = i >> 3, c = i & 7;
                cpa16(nstg + r*AROW + c*16,           nh + r*128 + c*16);
                cpa16(nstg + 64*AROW + r*AROW + c*16, nl + r*128 + c*16);
            }
            CP_COMMIT();
            asm volatile("cp.async.wait_group 1;" ::: "memory");
        } else {
            asm volatile("cp.async.wait_group 0;" ::: "memory");
        }
        __syncthreads();

        // transpose V tile: VS[k][d] -> VT[d][k] (hi & lo)
        {
            const uint32_t vsh = stg, vsl = stg + 64*AROW;
            const uint32_t vth = stg + 2*64*AROW, vtl = stg + 3*64*AROW;
#pragma unroll
            for (int i = t; i < 4096; i += 256) {
                int k = i >> 6, d = i & 63;
                uint16_t a, b2;
                asm volatile("ld.shared.u16 %0, [%1];" : "=h"(a)  : "r"(vsh + k*AROW + d*2));
                asm volatile("ld.shared.u16 %0, [%1];" : "=h"(b2) : "r"(vsl + k*AROW + d*2));
                asm volatile("st.shared.u16 [%0], %1;" :: "r"(vth + d*AROW + k*2), "h"(a));
                asm volatile("st.shared.u16 [%0], %1;" :: "r"(vtl + d*AROW + k*2), "h"(b2));
            }
        }
        __syncthreads();

        if (kt == 0) {
#pragma unroll
            for (int ks = 0; ks < 4; ks++) {
                const uint32_t ro = (wid*16 + lr)*AROW + ks*32 + lc;
                LDSM4(qfh[ks], sb + ro);
                LDSM4(qfl[ks], sb + SQ_L + ro);
            }
        }

        // ---- S = Q @ V^T
        float sc[8][4];
#pragma unroll
        for (int nt = 0; nt < 8; nt++)
#pragma unroll
            for (int r = 0; r < 4; r++) sc[nt][r] = 0.f;

#pragma unroll
        for (int ks = 0; ks < 4; ks++) {
            const uint32_t koff = ks*32 + lc;
#pragma unroll
            for (int h2 = 0; h2 < 4; h2++) {
                uint32_t bvh[4], bvl[4];
                const uint32_t ro = (h2*16 + lr)*AROW + koff;
                LDSM4(bvh, stg + ro);
                LDSM4(bvl, stg + 64*AROW + ro);
#pragma unroll
                for (int q = 0; q < 2; q++) {
                    const int nt = h2*2 + q;
                    MMA16816(sc[nt], qfh[ks], bvh[q], bvh[2+q]);
                    MMA16816(sc[nt], qfh[ks], bvl[q], bvl[2+q]);
                    MMA16816(sc[nt], qfl[ks], bvh[q], bvh[2+q]);
                }
            }
        }

        // ---- online softmax
#pragma unroll
        for (int i = 0; i < 2; i++) {
            float mx = -FLT_MAX;
#pragma unroll
            for (int nt = 0; nt < 8; nt++)
                mx = fmaxf(mx, fmaxf(sc[nt][2*i], sc[nt][2*i+1]));
            mx = fmaxf(mx, __shfl_xor_sync(0xffffffffu, mx, 1));
            mx = fmaxf(mx, __shfl_xor_sync(0xffffffffu, mx, 2));
            const float mnew = fmaxf(m[i], mx);
            const float alpha = __expf(m[i] - mnew);
            float rs = 0.f;
#pragma unroll
            for (int nt = 0; nt < 8; nt++) {
                sc[nt][2*i]   = __expf(sc[nt][2*i]   - mnew);
                sc[nt][2*i+1] = __expf(sc[nt][2*i+1] - mnew);
                rs += sc[nt][2*i] + sc[nt][2*i+1];
            }
            rs += __shfl_xor_sync(0xffffffffu, rs, 1);
            rs += __shfl_xor_sync(0xffffffffu, rs, 2);
            lsum[i] = lsum[i]*alpha + rs;
            m[i] = mnew;
#pragma unroll
            for (int nt = 0; nt < 8; nt++) {
                o[nt][2*i]   *= alpha;
                o[nt][2*i+1] *= alpha;
            }
        }

        // ---- pack P into A-fragments (hi/lo)
        uint32_t aph[4][4], apl[4][4];
#pragma unroll
        for (int k2 = 0; k2 < 4; k2++) {
            split2(sc[2*k2][0],   sc[2*k2][1],   aph[k2][0], apl[k2][0]);
            split2(sc[2*k2][2],   sc[2*k2][3],   aph[k2][1], apl[k2][1]);
            split2(sc[2*k2+1][0], sc[2*k2+1][1], aph[k2][2], apl[k2][2]);
            split2(sc[2*k2+1][2], sc[2*k2+1][3], aph[k2][3], apl[k2][3]);
        }

        // ---- O += P @ V
        const uint32_t vth = stg + 2*64*AROW, vtl = stg + 3*64*AROW;
#pragma unroll
        for (int k2 = 0; k2 < 4; k2++) {
            const uint32_t koff = k2*32 + lc;
#pragma unroll
            for (int h2 = 0; h2 < 4; h2++) {
                uint32_t bth[4], btl[4];
                const uint32_t ro = (h2*16 + lr)*AROW + koff;
                LDSM4(bth, vth + ro);
                LDSM4(btl, vtl + ro);
#pragma unroll
                for (int q = 0; q < 2; q++) {
                    const int nt = h2*2 + q;
                    MMA16816(o[nt], aph[k2], bth[q], bth[2+q]);
                    MMA16816(o[nt], apl[k2], bth[q], bth[2+q]);
                    MMA16816(o[nt], aph[k2], btl[q], btl[2+q]);
                }
            }
        }
        __syncthreads();
    }

    // ---- epilogue
    const int g = lane >> 2, qc = (lane & 3)*2;
    const int b = bh >> 4, h = bh & 15;
#pragma unroll
    for (int i = 0; i < 2; i++) {
        const float inv = 1.f / lsum[i];
        const int ltok = qt*128 + wid*16 + g + i*8;
        const size_t rowoff = (size_t)(b*SEQL + ltok)*EMB + h*DHEAD;
#pragma unroll
        for (int nt = 0; nt < 8; nt++) {
            uint32_t hp, lp;
            split2(o[nt][2*i]*inv, o[nt][2*i+1]*inv, hp, lp);
            *(uint32_t*)(ctxh + rowoff + nt*8 + qc) = hp;
            *(uint32_t*)(ctxl + rowoff + nt*8 + qc) = lp;
        }
    }
}

// ================= fused residual add + LayerNorm ===========================
template<bool HL>
__global__ __launch_bounds__(256)
void add_ln_kernel(const float* __restrict__ a, const float* __restrict__ bres,
                   const float* __restrict__ gamma, const float* __restrict__ beta,
                   float* __restrict__ out,
                   __nv_bfloat16* __restrict__ oh, __nv_bfloat16* __restrict__ ol)
{
    const int row = blockIdx.x;
    const int t = threadIdx.x;
    const int lane = t & 31, wid = t >> 5;

    const float4* ap = (const float4*)(a + (size_t)row * EMB);
    const float4* bp = (const float4*)(bres + (size_t)row * EMB);
    float4 av = ap[t], bv = bp[t];
    float v0 = av.x + bv.x, v1 = av.y + bv.y, v2 = av.z + bv.z, v3 = av.w + bv.w;

    float sum = v0 + v1 + v2 + v3;
    float sq  = v0*v0 + v1*v1 + v2*v2 + v3*v3;
#pragma unroll
    for (int off = 16; off >= 1; off >>= 1) {
        sum += __shfl_xor_sync(0xffffffffu, sum, off);
        sq  += __shfl_xor_sync(0xffffffffu, sq, off);
    }
    __shared__ float ssum[8], ssq[8], s_mean, s_rstd;
    if (lane == 0) { ssum[wid] = sum; ssq[wid] = sq; }
    __syncthreads();
    if (t == 0) {
        float S = 0.f, Q = 0.f;
#pragma unroll
        for (int w = 0; w < 8; w++) { S += ssum[w]; Q += ssq[w]; }
        float mean = S * (1.f/EMB);
        float var  = Q * (1.f/EMB) - mean*mean;
        s_mean = mean;
        s_rstd = rsqrtf(var + LN_EPS);
    }
    __syncthreads();
    const float mean = s_mean, rstd = s_rstd;

    float4 g = ((const float4*)gamma)[t], bt = ((const float4*)beta)[t];
    float4 r;
    r.x = (v0 - mean) * rstd * g.x + bt.x;
    r.y = (v1 - mean) * rstd * g.y + bt.y;
    r.z = (v2 - mean) * rstd * g.z + bt.z;
    r.w = (v3 - mean) * rstd * g.w + bt.w;
    ((float4*)(out + (size_t)row * EMB))[t] = r;

    if (HL) {
        size_t off = (size_t)row * EMB + 4*t;
        uint32_t h0, l0, h1, l1;
        split2(r.x, r.y, h0, l0);
        split2(r.z, r.w, h1, l1);
        *(uint32_t*)(oh + off)     = h0;
        *(uint32_t*)(oh + off + 2) = h1;
        *(uint32_t*)(ol + off)     = l0;
        *(uint32_t*)(ol + off + 2) = l1;
    }
}

// ================= launch ====================================================
extern "C" void kernel_launch(void* const* d_in, const int* in_sizes, int n_in,
                              void* d_out, int out_size)
{
    const float* x   = (const float*)d_in[0];
    const float* Wq  = (const float*)d_in[1];
    const float* bq  = (const float*)d_in[2];
    // d_in[3], d_in[4] = Wk, bk: dead code in the reference (scores use Q@V^T)
    const float* Wv  = (const float*)d_in[5];
    const float* bv  = (const float*)d_in[6];
    const float* Wo  = (const float*)d_in[7];
    const float* bo  = (const float*)d_in[8];
    const float* g1  = (const float*)d_in[9];
    const float* b1  = (const float*)d_in[10];
    const float* W1  = (const float*)d_in[11];
    const float* bf1 = (const float*)d_in[12];
    const float* W2  = (const float*)d_in[13];
    const float* bf2 = (const float*)d_in[14];
    const float* g2  = (const float*)d_in[15];
    const float* b2  = (const float*)d_in[16];
    float* out = (float*)d_out;

    __nv_bfloat16 *xh,*xl,*Wqvh,*Wqvl,*Woh,*Wol,*W1h,*W1l,*W2h,*W2l;
    __nv_bfloat16 *Qbh,*Qbl,*Vbh,*Vbl,*ctxh,*ctxl,*ph,*pl,*h1h,*h1l;
    float *attp,*postp,*ffp;
    cudaGetSymbolAddress((void**)&xh,  g_xh);  cudaGetSymbolAddress((void**)&xl,  g_xl);
    cudaGetSymbolAddress((void**)&Wqvh,g_Wqvh);cudaGetSymbolAddress((void**)&Wqvl,g_Wqvl);
    cudaGetSymbolAddress((void**)&Woh, g_Woh); cudaGetSymbolAddress((void**)&Wol, g_Wol);
    cudaGetSymbolAddress((void**)&W1h, g_W1h); cudaGetSymbolAddress((void**)&W1l, g_W1l);
    cudaGetSymbolAddress((void**)&W2h, g_W2h); cudaGetSymbolAddress((void**)&W2l, g_W2l);
    cudaGetSymbolAddress((void**)&Qbh, g_Qh);  cudaGetSymbolAddress((void**)&Qbl, g_Ql);
    cudaGetSymbolAddress((void**)&Vbh, g_Vh);  cudaGetSymbolAddress((void**)&Vbl, g_Vl);
    cudaGetSymbolAddress((void**)&ctxh,g_ctxh);cudaGetSymbolAddress((void**)&ctxl,g_ctxl);
    cudaGetSymbolAddress((void**)&attp,g_att); cudaGetSymbolAddress((void**)&postp,g_post);
    cudaGetSymbolAddress((void**)&ph,  g_ph);  cudaGetSymbolAddress((void**)&pl,  g_pl);
    cudaGetSymbolAddress((void**)&h1h, g_h1h); cudaGetSymbolAddress((void**)&h1l, g_h1l);
    cudaGetSymbolAddress((void**)&ffp, g_ff);

    cudaFuncSetAttribute(mma_gemm<EPI_PLAIN>,   cudaFuncAttributeMaxDynamicSharedMemorySize, GSMEM);
    cudaFuncSetAttribute(mma_gemm<EPI_RELU_HL>, cudaFuncAttributeMaxDynamicSharedMemorySize, GSMEM);
    cudaFuncSetAttribute(mma_gemm<EPI_QV>,      cudaFuncAttributeMaxDynamicSharedMemorySize, GSMEM);
    cudaFuncSetAttribute(attn_mma, cudaFuncAttributeMaxDynamicSharedMemorySize, ATT_SMEM);

    dim3 blk(256);
    dim3 tblk(32, 8);

    // input / weight conversion (hi/lo split; weights transposed to [N][K])
    convert_hl<<<NTOK*EMB/4/256, blk>>>((const float4*)x, xh, xl, NTOK*EMB/4);
    conv_transpose<<<dim3(EMB/32, EMB/32), tblk>>>(Wq, Wqvh, Wqvl, EMB, EMB);
    conv_transpose<<<dim3(EMB/32, EMB/32), tblk>>>(Wv, Wqvh + (size_t)EMB*EMB,
                                                   Wqvl + (size_t)EMB*EMB, EMB, EMB);
    conv_transpose<<<dim3(EMB/32, EMB/32), tblk>>>(Wo, Woh, Wol, EMB, EMB);
    conv_transpose<<<dim3(FFN/32, EMB/32), tblk>>>(W1, W1h, W1l, EMB, FFN);
    conv_transpose<<<dim3(EMB/32, FFN/32), tblk>>>(W2, W2h, W2l, FFN, EMB);

    // fused Q+V projection -> [b,h,l,d] bf16 hi/lo (Q pre-scaled by 1/8)
    mma_gemm<EPI_QV><<<dim3(2*EMB/256, NTOK/128), blk, GSMEM>>>(
        xh, xl, Wqvh, Wqvl, bq, bv, nullptr, Qbh, Qbl, Vbh, Vbl, NTOK, 2*EMB, EMB);

    // tensor-core flash attention -> ctx hi/lo [tok][E]
    attn_mma<<<dim3(SEQL/128, BATCH*HEADS), blk, ATT_SMEM>>>(Qbh, Qbl, Vbh, Vbl, ctxh, ctxl);

    // output projection -> att fp32
    mma_gemm<EPI_PLAIN><<<dim3(EMB/256, NTOK/128), blk, GSMEM>>>(
        ctxh, ctxl, Woh, Wol, bo, nullptr, attp, nullptr, nullptr, nullptr, nullptr,
        NTOK, EMB, EMB);

    // post = LN(x + att), plus hi/lo for FFN input
    add_ln_kernel<true><<<NTOK, blk>>>(x, attp, g1, b1, postp, ph, pl);

    // FFN
    mma_gemm<EPI_RELU_HL><<<dim3(FFN/256, NTOK/128), blk, GSMEM>>>(
        ph, pl, W1h, W1l, bf1, nullptr, nullptr, h1h, h1l, nullptr, nullptr,
        NTOK, FFN, EMB);
    mma_gemm<EPI_PLAIN><<<dim3(EMB/256, NTOK/128), blk, GSMEM>>>(
        h1h, h1l, W2h, W2l, bf2, nullptr, ffp, nullptr, nullptr, nullptr, nullptr,
        NTOK, EMB, FFN);

    // out = LN(post + ff)
    add_ln_kernel<false><<<NTOK, blk>>>(postp, ffp, g2, b2, out, nullptr, nullptr);
}